// round 1
// baseline (speedup 1.0000x reference)
#include <cuda_runtime.h>
#include <math.h>

// Problem constants
#define BB 2
#define TT 2048
#define DD 1024
#define HH 16
#define HD 64

// Scratch (device globals; no runtime allocation allowed)
__device__ float g_qkv[(size_t)BB * TT * 3 * DD]; // [B*T, 3D]  q|k|v
__device__ float g_att[(size_t)BB * TT * DD];     // [B*T, D]   attention output

// ---------------------------------------------------------------------------
// Classic 128x128x8 register-tiled SGEMM, 256 threads, 8x8 per thread.
// A: [M,K] row-major, B: [K,N] row-major, C: [M,N]. M%128==0, N%128==0, K%8==0.
// ---------------------------------------------------------------------------
__global__ __launch_bounds__(256) void sgemm128(const float* __restrict__ A,
                                                const float* __restrict__ B,
                                                float* __restrict__ C,
                                                int M, int N, int K)
{
    const int BM = 128, BN = 128, BK = 8, TM = 8, TN = 8;
    __shared__ float As[BK][BM];
    __shared__ float Bs[BK][BN];

    const int tid  = threadIdx.x;
    const int cRow = blockIdx.y;
    const int cCol = blockIdx.x;
    const int tr   = tid / 16;   // 0..15
    const int tc   = tid % 16;   // 0..15

    // global-load assignments
    const int aRow = tid >> 1;          // 0..127
    const int aCol = (tid & 1) * 4;     // 0 or 4
    const int bRow = tid >> 5;          // 0..7
    const int bCol = (tid & 31) * 4;    // 0..124

    const float* Ag = A + (size_t)cRow * BM * K;
    const float* Bg = B + (size_t)cCol * BN;

    float acc[TM][TN];
    #pragma unroll
    for (int m = 0; m < TM; m++)
        #pragma unroll
        for (int n = 0; n < TN; n++) acc[m][n] = 0.0f;

    float regM[TM], regN[TN];

    for (int k0 = 0; k0 < K; k0 += BK) {
        float4 a = *(const float4*)(Ag + (size_t)aRow * K + k0 + aCol);
        As[aCol + 0][aRow] = a.x;
        As[aCol + 1][aRow] = a.y;
        As[aCol + 2][aRow] = a.z;
        As[aCol + 3][aRow] = a.w;
        *(float4*)&Bs[bRow][bCol] =
            *(const float4*)(Bg + (size_t)(k0 + bRow) * N + bCol);
        __syncthreads();

        #pragma unroll
        for (int k = 0; k < BK; k++) {
            #pragma unroll
            for (int m = 0; m < TM; m++) regM[m] = As[k][tr * TM + m];
            #pragma unroll
            for (int n = 0; n < TN; n++) regN[n] = Bs[k][tc * TN + n];
            #pragma unroll
            for (int m = 0; m < TM; m++)
                #pragma unroll
                for (int n = 0; n < TN; n++)
                    acc[m][n] += regM[m] * regN[n];
        }
        __syncthreads();
    }

    float* Cg = C + (size_t)cRow * BM * N + cCol * BN;
    #pragma unroll
    for (int m = 0; m < TM; m++) {
        #pragma unroll
        for (int n = 0; n < TN; n += 4) {
            float4 v = make_float4(acc[m][n], acc[m][n + 1], acc[m][n + 2], acc[m][n + 3]);
            *(float4*)(Cg + (size_t)(tr * TM + m) * N + tc * TN + n) = v;
        }
    }
}

// ---------------------------------------------------------------------------
// RoPE applied in place to q and k halves of the qkv buffer.
// qkv: [B*T, 3D]; q at col h*64+d, k at 1024 + h*64+d.
// One thread per (bt, which, h, j) with j<32 handling the (j, j+32) pair.
// ---------------------------------------------------------------------------
__global__ __launch_bounds__(256) void rope_k(float* __restrict__ qkv)
{
    int idx = blockIdx.x * blockDim.x + threadIdx.x; // B*T*2*H*32 total
    int j     = idx & 31;
    int h     = (idx >> 5) & 15;
    int which = (idx >> 9) & 1;
    int bt    = idx >> 10;
    if (bt >= BB * TT) return;

    int t = bt & (TT - 1);
    float inv = powf(10000.0f, -(float)j * (1.0f / 32.0f));
    float ang = (float)t * inv;
    float s, c;
    sincosf(ang, &s, &c);

    float* base = qkv + (size_t)bt * (3 * DD) + which * DD + h * HD;
    float x1 = base[j];
    float x2 = base[j + 32];
    base[j]      = x1 * c - x2 * s;
    base[j + 32] = x2 * c + x1 * s;
}

// ---------------------------------------------------------------------------
// Causal flash attention. One block = one (b,h, 64-row q tile).
// 256 threads, 16x16 layout, 4x4 microtile. Online softmax. Causal tile skip.
// Dynamic smem: Qs/Ks/Vs/Ps, each 64 rows x stride 65 (pad against conflicts).
// ---------------------------------------------------------------------------
#define FPAD 65
#define FLASH_SMEM (4 * 64 * FPAD * 4)

__global__ __launch_bounds__(256) void flash_attn(const float* __restrict__ qkv,
                                                  float* __restrict__ out)
{
    extern __shared__ float sm[];
    float* Qs = sm;
    float* Ks = Qs + 64 * FPAD;
    float* Vs = Ks + 64 * FPAD;
    float* Ps = Vs + 64 * FPAD;

    const int qt = blockIdx.x;
    const int bh = blockIdx.y;
    const int b  = bh >> 4;
    const int h  = bh & 15;
    const int tid = threadIdx.x;
    const int tr  = tid >> 4;  // 0..15 -> q rows tr*4..tr*4+3
    const int tc  = tid & 15;  // 0..15 -> cols  tc*4..tc*4+3
    const float scale = 0.125f; // 1/sqrt(64)

    const int q0 = qt * 64;
    const float* qbase = qkv + ((size_t)(b * TT + q0)) * (3 * DD) + h * HD;

    // Load Q tile (64x64) into smem
    for (int i = tid; i < 64 * 16; i += 256) {
        int r  = i >> 4;
        int c4 = (i & 15) * 4;
        float4 v = *(const float4*)(qbase + (size_t)r * (3 * DD) + c4);
        float* dst = &Qs[r * FPAD + c4];
        dst[0] = v.x; dst[1] = v.y; dst[2] = v.z; dst[3] = v.w;
    }

    float o[4][4];
    float m_i[4], l_i[4];
    #pragma unroll
    for (int ii = 0; ii < 4; ii++) {
        m_i[ii] = -INFINITY;
        l_i[ii] = 0.0f;
        #pragma unroll
        for (int jj = 0; jj < 4; jj++) o[ii][jj] = 0.0f;
    }

    for (int kt = 0; kt <= qt; kt++) {
        const int k0 = kt * 64;
        const float* kbase = qkv + ((size_t)(b * TT + k0)) * (3 * DD) + DD + h * HD;
        const float* vbase = qkv + ((size_t)(b * TT + k0)) * (3 * DD) + 2 * DD + h * HD;

        __syncthreads(); // protect Ks/Vs/Ps from previous iteration readers
        for (int i = tid; i < 64 * 16; i += 256) {
            int r  = i >> 4;
            int c4 = (i & 15) * 4;
            float4 kv = *(const float4*)(kbase + (size_t)r * (3 * DD) + c4);
            float4 vv = *(const float4*)(vbase + (size_t)r * (3 * DD) + c4);
            float* kd = &Ks[r * FPAD + c4];
            float* vd = &Vs[r * FPAD + c4];
            kd[0] = kv.x; kd[1] = kv.y; kd[2] = kv.z; kd[3] = kv.w;
            vd[0] = vv.x; vd[1] = vv.y; vd[2] = vv.z; vd[3] = vv.w;
        }
        __syncthreads();

        // S = Q K^T (4x4 per thread)
        float sacc[4][4];
        #pragma unroll
        for (int ii = 0; ii < 4; ii++)
            #pragma unroll
            for (int jj = 0; jj < 4; jj++) sacc[ii][jj] = 0.0f;

        #pragma unroll 8
        for (int d = 0; d < 64; d++) {
            float qv[4], kv[4];
            #pragma unroll
            for (int ii = 0; ii < 4; ii++) qv[ii] = Qs[(tr * 4 + ii) * FPAD + d];
            #pragma unroll
            for (int jj = 0; jj < 4; jj++) kv[jj] = Ks[(tc * 4 + jj) * FPAD + d];
            #pragma unroll
            for (int ii = 0; ii < 4; ii++)
                #pragma unroll
                for (int jj = 0; jj < 4; jj++)
                    sacc[ii][jj] += qv[ii] * kv[jj];
        }

        // scale + causal mask
        #pragma unroll
        for (int ii = 0; ii < 4; ii++) {
            int qi = q0 + tr * 4 + ii;
            #pragma unroll
            for (int jj = 0; jj < 4; jj++) {
                int kj = k0 + tc * 4 + jj;
                sacc[ii][jj] = (kj > qi) ? -INFINITY : sacc[ii][jj] * scale;
            }
        }

        // online softmax per row (row spread across 16 lanes with same tr)
        #pragma unroll
        for (int ii = 0; ii < 4; ii++) {
            float mx = fmaxf(fmaxf(sacc[ii][0], sacc[ii][1]),
                             fmaxf(sacc[ii][2], sacc[ii][3]));
            #pragma unroll
            for (int off = 8; off > 0; off >>= 1)
                mx = fmaxf(mx, __shfl_xor_sync(0xffffffffu, mx, off));

            float newm  = fmaxf(m_i[ii], mx);
            float alpha = __expf(m_i[ii] - newm);

            float rs = 0.0f;
            #pragma unroll
            for (int jj = 0; jj < 4; jj++) {
                float p = __expf(sacc[ii][jj] - newm);
                sacc[ii][jj] = p;
                rs += p;
            }
            #pragma unroll
            for (int off = 8; off > 0; off >>= 1)
                rs += __shfl_xor_sync(0xffffffffu, rs, off);

            l_i[ii] = l_i[ii] * alpha + rs;
            m_i[ii] = newm;
            #pragma unroll
            for (int jj = 0; jj < 4; jj++) o[ii][jj] *= alpha;

            #pragma unroll
            for (int jj = 0; jj < 4; jj++)
                Ps[(tr * 4 + ii) * FPAD + tc * 4 + jj] = sacc[ii][jj];
        }
        __syncthreads();

        // O += P @ V (4x4 per thread over the same thread layout)
        #pragma unroll 8
        for (int j = 0; j < 64; j++) {
            float pv[4], vv[4];
            #pragma unroll
            for (int ii = 0; ii < 4; ii++) pv[ii] = Ps[(tr * 4 + ii) * FPAD + j];
            #pragma unroll
            for (int jj = 0; jj < 4; jj++) vv[jj] = Vs[j * FPAD + tc * 4 + jj];
            #pragma unroll
            for (int ii = 0; ii < 4; ii++)
                #pragma unroll
                for (int jj = 0; jj < 4; jj++)
                    o[ii][jj] += pv[ii] * vv[jj];
        }
    }

    // normalize + write out [B,T,D]
    #pragma unroll
    for (int ii = 0; ii < 4; ii++) {
        float inv = 1.0f / l_i[ii];
        float4 v = make_float4(o[ii][0] * inv, o[ii][1] * inv,
                               o[ii][2] * inv, o[ii][3] * inv);
        size_t row = (size_t)(b * TT + q0 + tr * 4 + ii);
        *(float4*)(out + row * DD + h * HD + tc * 4) = v;
    }
}

// ---------------------------------------------------------------------------
extern "C" void kernel_launch(void* const* d_in, const int* in_sizes, int n_in,
                              void* d_out, int out_size)
{
    const float* x     = (const float*)d_in[0]; // [B,T,D]
    const float* w_qkv = (const float*)d_in[1]; // [D,3D]
    const float* w_out = (const float*)d_in[2]; // [D,D]
    float* out = (float*)d_out;                 // [B,T,D]

    float *qkv, *att;
    cudaGetSymbolAddress((void**)&qkv, g_qkv);
    cudaGetSymbolAddress((void**)&att, g_att);

    cudaFuncSetAttribute(flash_attn, cudaFuncAttributeMaxDynamicSharedMemorySize,
                         FLASH_SMEM);

    dim3 blk(256);
    const int M = BB * TT; // 4096

    // 1. qkv = x @ w_qkv
    sgemm128<<<dim3((3 * DD) / 128, M / 128), blk>>>(x, w_qkv, qkv, M, 3 * DD, DD);
    // 2. RoPE on q,k in place
    rope_k<<<(M * 2 * HH * 32) / 256, blk>>>(qkv);
    // 3. causal flash attention -> att [B,T,D]
    flash_attn<<<dim3(TT / 64, BB * HH), blk, FLASH_SMEM>>>(qkv, att);
    // 4. out = att @ w_out
    sgemm128<<<dim3(DD / 128, M / 128), blk>>>(att, w_out, out, M, DD, DD);
}

// round 2
// speedup vs baseline: 1.4442x; 1.4442x over previous
#include <cuda_runtime.h>
#include <math.h>

// Problem constants
#define BB 2
#define TT 2048
#define DD 1024
#define HH 16
#define HD 64

// Scratch (device globals; no runtime allocation allowed)
__device__ float g_qkv[(size_t)BB * TT * 3 * DD]; // [B*T, 3D]  q|k|v
__device__ float g_att[(size_t)BB * TT * DD];     // [B*T, D]   attention output

// ---------------------------------------------------------------------------
// TF32 tensor-core GEMM: C[M,N] = A[M,K] @ B[K,N], all row-major fp32.
// mma.sync.aligned.m16n8k8 tf32. Block tile 128x128x16, 256 threads (8 warps),
// warp tile 64x32 (4x4 mma tiles). Requires M%128==0, N%128==0, K%16==0.
// ---------------------------------------------------------------------------
#define GBM 128
#define GBN 128
#define GBK 16

__device__ __forceinline__ unsigned f2tf32(float f) {
    unsigned r;
    asm("cvt.rna.tf32.f32 %0, %1;" : "=r"(r) : "f"(f));
    return r;
}

__device__ __forceinline__ void mma_tf32(float c[4], unsigned a0, unsigned a1,
                                         unsigned a2, unsigned a3,
                                         unsigned b0, unsigned b1) {
    asm volatile(
        "mma.sync.aligned.m16n8k8.row.col.f32.tf32.tf32.f32 "
        "{%0,%1,%2,%3}, {%4,%5,%6,%7}, {%8,%9}, {%0,%1,%2,%3};\n"
        : "+f"(c[0]), "+f"(c[1]), "+f"(c[2]), "+f"(c[3])
        : "r"(a0), "r"(a1), "r"(a2), "r"(a3), "r"(b0), "r"(b1));
}

__global__ __launch_bounds__(256) void gemm_tf32(const float* __restrict__ A,
                                                 const float* __restrict__ B,
                                                 float* __restrict__ C,
                                                 int M, int N, int K)
{
    __shared__ unsigned As[GBM][GBK + 1];  // [m][k], tf32 bits
    __shared__ unsigned Bs[GBK][GBN + 4];  // [k][n], tf32 bits

    const int tid  = threadIdx.x;
    const int warp = tid >> 5;
    const int lane = tid & 31;
    const int wm   = warp >> 2;   // 0..1 : warp row (64 rows each)
    const int wn   = warp & 3;    // 0..3 : warp col (32 cols each)
    const int gid  = lane >> 2;   // 0..7
    const int tig  = lane & 3;    // 0..3

    const int cRow = blockIdx.y * GBM;
    const int cCol = blockIdx.x * GBN;

    // global-load assignments
    const int aR  = tid >> 2;          // 0..63 (and +64)
    const int aC  = (tid & 3) * 4;     // 0,4,8,12
    const int bR  = tid >> 5;          // 0..7 (and +8)
    const int bC  = (lane) * 4;        // 0..124

    float c[4][4][4];
    #pragma unroll
    for (int mt = 0; mt < 4; mt++)
        #pragma unroll
        for (int nt = 0; nt < 4; nt++)
            #pragma unroll
            for (int r = 0; r < 4; r++) c[mt][nt][r] = 0.0f;

    for (int k0 = 0; k0 < K; k0 += GBK) {
        // load A 128x16
        {
            float4 v0 = *(const float4*)(A + (size_t)(cRow + aR) * K + k0 + aC);
            float4 v1 = *(const float4*)(A + (size_t)(cRow + aR + 64) * K + k0 + aC);
            As[aR][aC + 0] = f2tf32(v0.x); As[aR][aC + 1] = f2tf32(v0.y);
            As[aR][aC + 2] = f2tf32(v0.z); As[aR][aC + 3] = f2tf32(v0.w);
            As[aR + 64][aC + 0] = f2tf32(v1.x); As[aR + 64][aC + 1] = f2tf32(v1.y);
            As[aR + 64][aC + 2] = f2tf32(v1.z); As[aR + 64][aC + 3] = f2tf32(v1.w);
        }
        // load B 16x128
        {
            float4 v0 = *(const float4*)(B + (size_t)(k0 + bR) * N + cCol + bC);
            float4 v1 = *(const float4*)(B + (size_t)(k0 + bR + 8) * N + cCol + bC);
            Bs[bR][bC + 0] = f2tf32(v0.x); Bs[bR][bC + 1] = f2tf32(v0.y);
            Bs[bR][bC + 2] = f2tf32(v0.z); Bs[bR][bC + 3] = f2tf32(v0.w);
            Bs[bR + 8][bC + 0] = f2tf32(v1.x); Bs[bR + 8][bC + 1] = f2tf32(v1.y);
            Bs[bR + 8][bC + 2] = f2tf32(v1.z); Bs[bR + 8][bC + 3] = f2tf32(v1.w);
        }
        __syncthreads();

        #pragma unroll
        for (int ks = 0; ks < GBK; ks += 8) {
            unsigned af[4][4], bf[4][2];
            #pragma unroll
            for (int mt = 0; mt < 4; mt++) {
                int row = wm * 64 + mt * 16;
                af[mt][0] = As[row + gid    ][ks + tig    ];
                af[mt][1] = As[row + gid + 8][ks + tig    ];
                af[mt][2] = As[row + gid    ][ks + tig + 4];
                af[mt][3] = As[row + gid + 8][ks + tig + 4];
            }
            #pragma unroll
            for (int nt = 0; nt < 4; nt++) {
                int col = wn * 32 + nt * 8;
                bf[nt][0] = Bs[ks + tig    ][col + gid];
                bf[nt][1] = Bs[ks + tig + 4][col + gid];
            }
            #pragma unroll
            for (int mt = 0; mt < 4; mt++)
                #pragma unroll
                for (int nt = 0; nt < 4; nt++)
                    mma_tf32(c[mt][nt], af[mt][0], af[mt][1], af[mt][2], af[mt][3],
                             bf[nt][0], bf[nt][1]);
        }
        __syncthreads();
    }

    // epilogue
    #pragma unroll
    for (int mt = 0; mt < 4; mt++) {
        #pragma unroll
        for (int nt = 0; nt < 4; nt++) {
            int row = cRow + wm * 64 + mt * 16 + gid;
            int col = cCol + wn * 32 + nt * 8 + tig * 2;
            *(float2*)(C + (size_t)row * N + col) =
                make_float2(c[mt][nt][0], c[mt][nt][1]);
            *(float2*)(C + (size_t)(row + 8) * N + col) =
                make_float2(c[mt][nt][2], c[mt][nt][3]);
        }
    }
}

// ---------------------------------------------------------------------------
// RoPE applied in place to q and k halves of the qkv buffer.
// ---------------------------------------------------------------------------
__global__ __launch_bounds__(256) void rope_k(float* __restrict__ qkv)
{
    int idx = blockIdx.x * blockDim.x + threadIdx.x; // B*T*2*H*32 total
    int j     = idx & 31;
    int h     = (idx >> 5) & 15;
    int which = (idx >> 9) & 1;
    int bt    = idx >> 10;
    if (bt >= BB * TT) return;

    int t = bt & (TT - 1);
    float inv = powf(10000.0f, -(float)j * (1.0f / 32.0f));
    float ang = (float)t * inv;
    float s, c;
    sincosf(ang, &s, &c);

    float* base = qkv + (size_t)bt * (3 * DD) + which * DD + h * HD;
    float x1 = base[j];
    float x2 = base[j + 32];
    base[j]      = x1 * c - x2 * s;
    base[j + 32] = x2 * c + x1 * s;
}

// ---------------------------------------------------------------------------
// Causal flash attention (unchanged from R1 baseline).
// ---------------------------------------------------------------------------
#define FPAD 65
#define FLASH_SMEM (4 * 64 * FPAD * 4)

__global__ __launch_bounds__(256) void flash_attn(const float* __restrict__ qkv,
                                                  float* __restrict__ out)
{
    extern __shared__ float sm[];
    float* Qs = sm;
    float* Ks = Qs + 64 * FPAD;
    float* Vs = Ks + 64 * FPAD;
    float* Ps = Vs + 64 * FPAD;

    const int qt = blockIdx.x;
    const int bh = blockIdx.y;
    const int b  = bh >> 4;
    const int h  = bh & 15;
    const int tid = threadIdx.x;
    const int tr  = tid >> 4;
    const int tc  = tid & 15;
    const float scale = 0.125f;

    const int q0 = qt * 64;
    const float* qbase = qkv + ((size_t)(b * TT + q0)) * (3 * DD) + h * HD;

    for (int i = tid; i < 64 * 16; i += 256) {
        int r  = i >> 4;
        int c4 = (i & 15) * 4;
        float4 v = *(const float4*)(qbase + (size_t)r * (3 * DD) + c4);
        float* dst = &Qs[r * FPAD + c4];
        dst[0] = v.x; dst[1] = v.y; dst[2] = v.z; dst[3] = v.w;
    }

    float o[4][4];
    float m_i[4], l_i[4];
    #pragma unroll
    for (int ii = 0; ii < 4; ii++) {
        m_i[ii] = -INFINITY;
        l_i[ii] = 0.0f;
        #pragma unroll
        for (int jj = 0; jj < 4; jj++) o[ii][jj] = 0.0f;
    }

    for (int kt = 0; kt <= qt; kt++) {
        const int k0 = kt * 64;
        const float* kbase = qkv + ((size_t)(b * TT + k0)) * (3 * DD) + DD + h * HD;
        const float* vbase = qkv + ((size_t)(b * TT + k0)) * (3 * DD) + 2 * DD + h * HD;

        __syncthreads();
        for (int i = tid; i < 64 * 16; i += 256) {
            int r  = i >> 4;
            int c4 = (i & 15) * 4;
            float4 kv = *(const float4*)(kbase + (size_t)r * (3 * DD) + c4);
            float4 vv = *(const float4*)(vbase + (size_t)r * (3 * DD) + c4);
            float* kd = &Ks[r * FPAD + c4];
            float* vd = &Vs[r * FPAD + c4];
            kd[0] = kv.x; kd[1] = kv.y; kd[2] = kv.z; kd[3] = kv.w;
            vd[0] = vv.x; vd[1] = vv.y; vd[2] = vv.z; vd[3] = vv.w;
        }
        __syncthreads();

        float sacc[4][4];
        #pragma unroll
        for (int ii = 0; ii < 4; ii++)
            #pragma unroll
            for (int jj = 0; jj < 4; jj++) sacc[ii][jj] = 0.0f;

        #pragma unroll 8
        for (int d = 0; d < 64; d++) {
            float qv[4], kv[4];
            #pragma unroll
            for (int ii = 0; ii < 4; ii++) qv[ii] = Qs[(tr * 4 + ii) * FPAD + d];
            #pragma unroll
            for (int jj = 0; jj < 4; jj++) kv[jj] = Ks[(tc * 4 + jj) * FPAD + d];
            #pragma unroll
            for (int ii = 0; ii < 4; ii++)
                #pragma unroll
                for (int jj = 0; jj < 4; jj++)
                    sacc[ii][jj] += qv[ii] * kv[jj];
        }

        #pragma unroll
        for (int ii = 0; ii < 4; ii++) {
            int qi = q0 + tr * 4 + ii;
            #pragma unroll
            for (int jj = 0; jj < 4; jj++) {
                int kj = k0 + tc * 4 + jj;
                sacc[ii][jj] = (kj > qi) ? -INFINITY : sacc[ii][jj] * scale;
            }
        }

        #pragma unroll
        for (int ii = 0; ii < 4; ii++) {
            float mx = fmaxf(fmaxf(sacc[ii][0], sacc[ii][1]),
                             fmaxf(sacc[ii][2], sacc[ii][3]));
            #pragma unroll
            for (int off = 8; off > 0; off >>= 1)
                mx = fmaxf(mx, __shfl_xor_sync(0xffffffffu, mx, off));

            float newm  = fmaxf(m_i[ii], mx);
            float alpha = __expf(m_i[ii] - newm);

            float rs = 0.0f;
            #pragma unroll
            for (int jj = 0; jj < 4; jj++) {
                float p = __expf(sacc[ii][jj] - newm);
                sacc[ii][jj] = p;
                rs += p;
            }
            #pragma unroll
            for (int off = 8; off > 0; off >>= 1)
                rs += __shfl_xor_sync(0xffffffffu, rs, off);

            l_i[ii] = l_i[ii] * alpha + rs;
            m_i[ii] = newm;
            #pragma unroll
            for (int jj = 0; jj < 4; jj++) o[ii][jj] *= alpha;

            #pragma unroll
            for (int jj = 0; jj < 4; jj++)
                Ps[(tr * 4 + ii) * FPAD + tc * 4 + jj] = sacc[ii][jj];
        }
        __syncthreads();

        #pragma unroll 8
        for (int j = 0; j < 64; j++) {
            float pv[4], vv[4];
            #pragma unroll
            for (int ii = 0; ii < 4; ii++) pv[ii] = Ps[(tr * 4 + ii) * FPAD + j];
            #pragma unroll
            for (int jj = 0; jj < 4; jj++) vv[jj] = Vs[j * FPAD + tc * 4 + jj];
            #pragma unroll
            for (int ii = 0; ii < 4; ii++)
                #pragma unroll
                for (int jj = 0; jj < 4; jj++)
                    o[ii][jj] += pv[ii] * vv[jj];
        }
    }

    #pragma unroll
    for (int ii = 0; ii < 4; ii++) {
        float inv = 1.0f / l_i[ii];
        float4 v = make_float4(o[ii][0] * inv, o[ii][1] * inv,
                               o[ii][2] * inv, o[ii][3] * inv);
        size_t row = (size_t)(b * TT + q0 + tr * 4 + ii);
        *(float4*)(out + row * DD + h * HD + tc * 4) = v;
    }
}

// ---------------------------------------------------------------------------
extern "C" void kernel_launch(void* const* d_in, const int* in_sizes, int n_in,
                              void* d_out, int out_size)
{
    const float* x     = (const float*)d_in[0]; // [B,T,D]
    const float* w_qkv = (const float*)d_in[1]; // [D,3D]
    const float* w_out = (const float*)d_in[2]; // [D,D]
    float* out = (float*)d_out;                 // [B,T,D]

    float *qkv, *att;
    cudaGetSymbolAddress((void**)&qkv, g_qkv);
    cudaGetSymbolAddress((void**)&att, g_att);

    cudaFuncSetAttribute(flash_attn, cudaFuncAttributeMaxDynamicSharedMemorySize,
                         FLASH_SMEM);

    dim3 blk(256);
    const int M = BB * TT; // 4096

    // 1. qkv = x @ w_qkv  (tf32 tensor cores)
    gemm_tf32<<<dim3((3 * DD) / GBN, M / GBM), blk>>>(x, w_qkv, qkv, M, 3 * DD, DD);
    // 2. RoPE on q,k in place
    rope_k<<<(M * 2 * HH * 32) / 256, blk>>>(qkv);
    // 3. causal flash attention -> att [B,T,D]
    flash_attn<<<dim3(TT / 64, BB * HH), blk, FLASH_SMEM>>>(qkv, att);
    // 4. out = att @ w_out  (tf32 tensor cores)
    gemm_tf32<<<dim3(DD / GBN, M / GBM), blk>>>(att, w_out, out, M, DD, DD);
}

// round 4
// speedup vs baseline: 2.5485x; 1.7646x over previous
#include <cuda_runtime.h>
#include <math.h>

// Problem constants
#define BB 2
#define TT 2048
#define DD 1024
#define HH 16
#define HD 64

// Scratch (device globals; no runtime allocation allowed)
__device__ float g_qkv[(size_t)BB * TT * 3 * DD]; // [B*T, 3D]  q|k|v
__device__ float g_att[(size_t)BB * TT * DD];     // [B*T, D]   attention output

__device__ __forceinline__ unsigned f2tf32(float f) {
    unsigned r;
    asm("cvt.rna.tf32.f32 %0, %1;" : "=r"(r) : "f"(f));
    return r;
}

__device__ __forceinline__ void mma_tf32(float c[4], unsigned a0, unsigned a1,
                                         unsigned a2, unsigned a3,
                                         unsigned b0, unsigned b1) {
    asm volatile(
        "mma.sync.aligned.m16n8k8.row.col.f32.tf32.tf32.f32 "
        "{%0,%1,%2,%3}, {%4,%5,%6,%7}, {%8,%9}, {%0,%1,%2,%3};\n"
        : "+f"(c[0]), "+f"(c[1]), "+f"(c[2]), "+f"(c[3])
        : "r"(a0), "r"(a1), "r"(a2), "r"(a3), "r"(b0), "r"(b1));
}

// ---------------------------------------------------------------------------
// TF32 tensor-core GEMM: C[M,N] = A[M,K] @ B[K,N], all row-major fp32.
// Block tile 128x128x16, 256 threads (8 warps), warp tile 64x32.
// ---------------------------------------------------------------------------
#define GBM 128
#define GBN 128
#define GBK 16

__global__ __launch_bounds__(256) void gemm_tf32(const float* __restrict__ A,
                                                 const float* __restrict__ B,
                                                 float* __restrict__ C,
                                                 int M, int N, int K)
{
    __shared__ unsigned As[GBM][GBK + 1];
    __shared__ unsigned Bs[GBK][GBN + 4];

    const int tid  = threadIdx.x;
    const int warp = tid >> 5;
    const int lane = tid & 31;
    const int wm   = warp >> 2;
    const int wn   = warp & 3;
    const int gid  = lane >> 2;
    const int tig  = lane & 3;

    const int cRow = blockIdx.y * GBM;
    const int cCol = blockIdx.x * GBN;

    const int aR  = tid >> 2;
    const int aC  = (tid & 3) * 4;
    const int bR  = tid >> 5;
    const int bC  = (lane) * 4;

    float c[4][4][4];
    #pragma unroll
    for (int mt = 0; mt < 4; mt++)
        #pragma unroll
        for (int nt = 0; nt < 4; nt++)
            #pragma unroll
            for (int r = 0; r < 4; r++) c[mt][nt][r] = 0.0f;

    for (int k0 = 0; k0 < K; k0 += GBK) {
        {
            float4 v0 = *(const float4*)(A + (size_t)(cRow + aR) * K + k0 + aC);
            float4 v1 = *(const float4*)(A + (size_t)(cRow + aR + 64) * K + k0 + aC);
            As[aR][aC + 0] = f2tf32(v0.x); As[aR][aC + 1] = f2tf32(v0.y);
            As[aR][aC + 2] = f2tf32(v0.z); As[aR][aC + 3] = f2tf32(v0.w);
            As[aR + 64][aC + 0] = f2tf32(v1.x); As[aR + 64][aC + 1] = f2tf32(v1.y);
            As[aR + 64][aC + 2] = f2tf32(v1.z); As[aR + 64][aC + 3] = f2tf32(v1.w);
        }
        {
            float4 v0 = *(const float4*)(B + (size_t)(k0 + bR) * N + cCol + bC);
            float4 v1 = *(const float4*)(B + (size_t)(k0 + bR + 8) * N + cCol + bC);
            Bs[bR][bC + 0] = f2tf32(v0.x); Bs[bR][bC + 1] = f2tf32(v0.y);
            Bs[bR][bC + 2] = f2tf32(v0.z); Bs[bR][bC + 3] = f2tf32(v0.w);
            Bs[bR + 8][bC + 0] = f2tf32(v1.x); Bs[bR + 8][bC + 1] = f2tf32(v1.y);
            Bs[bR + 8][bC + 2] = f2tf32(v1.z); Bs[bR + 8][bC + 3] = f2tf32(v1.w);
        }
        __syncthreads();

        #pragma unroll
        for (int ks = 0; ks < GBK; ks += 8) {
            unsigned af[4][4], bf[4][2];
            #pragma unroll
            for (int mt = 0; mt < 4; mt++) {
                int row = wm * 64 + mt * 16;
                af[mt][0] = As[row + gid    ][ks + tig    ];
                af[mt][1] = As[row + gid + 8][ks + tig    ];
                af[mt][2] = As[row + gid    ][ks + tig + 4];
                af[mt][3] = As[row + gid + 8][ks + tig + 4];
            }
            #pragma unroll
            for (int nt = 0; nt < 4; nt++) {
                int col = wn * 32 + nt * 8;
                bf[nt][0] = Bs[ks + tig    ][col + gid];
                bf[nt][1] = Bs[ks + tig + 4][col + gid];
            }
            #pragma unroll
            for (int mt = 0; mt < 4; mt++)
                #pragma unroll
                for (int nt = 0; nt < 4; nt++)
                    mma_tf32(c[mt][nt], af[mt][0], af[mt][1], af[mt][2], af[mt][3],
                             bf[nt][0], bf[nt][1]);
        }
        __syncthreads();
    }

    #pragma unroll
    for (int mt = 0; mt < 4; mt++) {
        #pragma unroll
        for (int nt = 0; nt < 4; nt++) {
            int row = cRow + wm * 64 + mt * 16 + gid;
            int col = cCol + wn * 32 + nt * 8 + tig * 2;
            *(float2*)(C + (size_t)row * N + col) =
                make_float2(c[mt][nt][0], c[mt][nt][1]);
            *(float2*)(C + (size_t)(row + 8) * N + col) =
                make_float2(c[mt][nt][2], c[mt][nt][3]);
        }
    }
}

// ---------------------------------------------------------------------------
// RoPE applied in place to q and k halves of the qkv buffer.
// ---------------------------------------------------------------------------
__global__ __launch_bounds__(256) void rope_k(float* __restrict__ qkv)
{
    int idx = blockIdx.x * blockDim.x + threadIdx.x;
    int j     = idx & 31;
    int h     = (idx >> 5) & 15;
    int which = (idx >> 9) & 1;
    int bt    = idx >> 10;
    if (bt >= BB * TT) return;

    int t = bt & (TT - 1);
    float inv = powf(10000.0f, -(float)j * (1.0f / 32.0f));
    float ang = (float)t * inv;
    float s, c;
    sincosf(ang, &s, &c);

    float* base = qkv + (size_t)bt * (3 * DD) + which * DD + h * HD;
    float x1 = base[j];
    float x2 = base[j + 32];
    base[j]      = x1 * c - x2 * s;
    base[j + 32] = x2 * c + x1 * s;
}

// ---------------------------------------------------------------------------
// Causal flash attention on tensor cores (tf32 m16n8k8).
// Block = 64 q-rows of one (b,h). 128 threads, 4 warps; warp w owns q rows
// [w*16, w*16+16) x all 64 k-cols -> softmax row stats are warp-local.
// Smem tiles hold tf32 bits, stride 68 => conflict-free fragment loads.
// Ps aliases Qs (Q fragments are register-resident after the prologue).
// ---------------------------------------------------------------------------
#define FS 68
#define FLASH2_SMEM (3 * 64 * FS * 4)

__global__ __launch_bounds__(128) void flash_mma(const float* __restrict__ qkv,
                                                 float* __restrict__ out)
{
    extern __shared__ unsigned smu[];
    unsigned* Qs = smu;            // [64][FS]  (aliased with Ps)
    unsigned* Ps = smu;
    unsigned* Ks = smu + 64 * FS;  // [64][FS]
    unsigned* Vs = smu + 2 * 64 * FS;

    const int qt = blockIdx.x;
    const int bh = blockIdx.y;
    const int b  = bh >> 4;
    const int h  = bh & 15;
    const int tid  = threadIdx.x;
    const int warp = tid >> 5;
    const int lane = tid & 31;
    const int gid  = lane >> 2;   // 0..7
    const int tig  = lane & 3;    // 0..3
    const int rbase = warp * 16;
    const float scale = 0.125f;   // 1/sqrt(64)

    const int q0 = qt * 64;
    const float* qbase = qkv + ((size_t)(b * TT + q0)) * (3 * DD) + h * HD;

    // Prologue: Q tile -> smem (tf32), then Q fragments -> registers
    for (int i = tid; i < 64 * 16; i += 128) {
        int r  = i >> 4;
        int c4 = (i & 15) * 4;
        float4 v = *(const float4*)(qbase + (size_t)r * (3 * DD) + c4);
        uint4 u = make_uint4(f2tf32(v.x), f2tf32(v.y), f2tf32(v.z), f2tf32(v.w));
        *(uint4*)&Qs[r * FS + c4] = u;
    }
    __syncthreads();

    unsigned qf[8][4];
    #pragma unroll
    for (int ks = 0; ks < 8; ks++) {
        qf[ks][0] = Qs[(rbase + gid    ) * FS + ks * 8 + tig    ];
        qf[ks][1] = Qs[(rbase + gid + 8) * FS + ks * 8 + tig    ];
        qf[ks][2] = Qs[(rbase + gid    ) * FS + ks * 8 + tig + 4];
        qf[ks][3] = Qs[(rbase + gid + 8) * FS + ks * 8 + tig + 4];
    }

    float o[8][4];
    #pragma unroll
    for (int nt = 0; nt < 8; nt++)
        #pragma unroll
        for (int r = 0; r < 4; r++) o[nt][r] = 0.0f;
    float m_lo = -INFINITY, m_hi = -INFINITY;
    float l_lo = 0.0f, l_hi = 0.0f;

    const int row_lo = q0 + rbase + gid;      // global q row (lo half)
    const int row_hi = row_lo + 8;

    for (int kt = 0; kt <= qt; kt++) {
        const int k0 = kt * 64;
        const float* kbase = qkv + ((size_t)(b * TT + k0)) * (3 * DD) + DD + h * HD;
        const float* vbase = qkv + ((size_t)(b * TT + k0)) * (3 * DD) + 2 * DD + h * HD;

        __syncthreads();   // everyone done reading Ks/Vs from prev iter
        for (int i = tid; i < 64 * 16; i += 128) {
            int r  = i >> 4;
            int c4 = (i & 15) * 4;
            float4 kv = *(const float4*)(kbase + (size_t)r * (3 * DD) + c4);
            float4 vv = *(const float4*)(vbase + (size_t)r * (3 * DD) + c4);
            *(uint4*)&Ks[r * FS + c4] =
                make_uint4(f2tf32(kv.x), f2tf32(kv.y), f2tf32(kv.z), f2tf32(kv.w));
            *(uint4*)&Vs[r * FS + c4] =
                make_uint4(f2tf32(vv.x), f2tf32(vv.y), f2tf32(vv.z), f2tf32(vv.w));
        }
        __syncthreads();

        // S = Q K^T : warp computes 16x64
        float s[8][4];
        #pragma unroll
        for (int nt = 0; nt < 8; nt++)
            #pragma unroll
            for (int r = 0; r < 4; r++) s[nt][r] = 0.0f;

        #pragma unroll
        for (int ks = 0; ks < 8; ks++) {
            #pragma unroll
            for (int nt = 0; nt < 8; nt++) {
                unsigned b0 = Ks[(nt * 8 + gid) * FS + ks * 8 + tig    ];
                unsigned b1 = Ks[(nt * 8 + gid) * FS + ks * 8 + tig + 4];
                mma_tf32(s[nt], qf[ks][0], qf[ks][1], qf[ks][2], qf[ks][3], b0, b1);
            }
        }

        // scale (+ causal mask on the diagonal tile)
        if (kt == qt) {
            #pragma unroll
            for (int nt = 0; nt < 8; nt++) {
                int c0 = k0 + nt * 8 + tig * 2;
                s[nt][0] = (c0     > row_lo) ? -INFINITY : s[nt][0] * scale;
                s[nt][1] = (c0 + 1 > row_lo) ? -INFINITY : s[nt][1] * scale;
                s[nt][2] = (c0     > row_hi) ? -INFINITY : s[nt][2] * scale;
                s[nt][3] = (c0 + 1 > row_hi) ? -INFINITY : s[nt][3] * scale;
            }
        } else {
            #pragma unroll
            for (int nt = 0; nt < 8; nt++)
                #pragma unroll
                for (int r = 0; r < 4; r++) s[nt][r] *= scale;
        }

        // online softmax: rows gid (lo) and gid+8 (hi); reduce over tig group
        float mx_lo = -INFINITY, mx_hi = -INFINITY;
        #pragma unroll
        for (int nt = 0; nt < 8; nt++) {
            mx_lo = fmaxf(mx_lo, fmaxf(s[nt][0], s[nt][1]));
            mx_hi = fmaxf(mx_hi, fmaxf(s[nt][2], s[nt][3]));
        }
        #pragma unroll
        for (int off = 1; off <= 2; off <<= 1) {
            mx_lo = fmaxf(mx_lo, __shfl_xor_sync(0xffffffffu, mx_lo, off));
            mx_hi = fmaxf(mx_hi, __shfl_xor_sync(0xffffffffu, mx_hi, off));
        }

        float newm_lo = fmaxf(m_lo, mx_lo);
        float newm_hi = fmaxf(m_hi, mx_hi);
        float alpha_lo = __expf(m_lo - newm_lo);
        float alpha_hi = __expf(m_hi - newm_hi);

        float sum_lo = 0.0f, sum_hi = 0.0f;
        #pragma unroll
        for (int nt = 0; nt < 8; nt++) {
            s[nt][0] = __expf(s[nt][0] - newm_lo);
            s[nt][1] = __expf(s[nt][1] - newm_lo);
            s[nt][2] = __expf(s[nt][2] - newm_hi);
            s[nt][3] = __expf(s[nt][3] - newm_hi);
            sum_lo += s[nt][0] + s[nt][1];
            sum_hi += s[nt][2] + s[nt][3];
        }
        #pragma unroll
        for (int off = 1; off <= 2; off <<= 1) {
            sum_lo += __shfl_xor_sync(0xffffffffu, sum_lo, off);
            sum_hi += __shfl_xor_sync(0xffffffffu, sum_hi, off);
        }

        l_lo = l_lo * alpha_lo + sum_lo;
        l_hi = l_hi * alpha_hi + sum_hi;
        m_lo = newm_lo;
        m_hi = newm_hi;

        #pragma unroll
        for (int nt = 0; nt < 8; nt++) {
            o[nt][0] *= alpha_lo; o[nt][1] *= alpha_lo;
            o[nt][2] *= alpha_hi; o[nt][3] *= alpha_hi;
        }

        // P -> smem (tf32 bits); warp-private rows, so __syncwarp suffices
        #pragma unroll
        for (int nt = 0; nt < 8; nt++) {
            int cc = nt * 8 + tig * 2;
            *(uint2*)&Ps[(rbase + gid    ) * FS + cc] =
                make_uint2(f2tf32(s[nt][0]), f2tf32(s[nt][1]));
            *(uint2*)&Ps[(rbase + gid + 8) * FS + cc] =
                make_uint2(f2tf32(s[nt][2]), f2tf32(s[nt][3]));
        }
        __syncwarp();

        // O += P @ V
        #pragma unroll
        for (int ks = 0; ks < 8; ks++) {
            unsigned a0 = Ps[(rbase + gid    ) * FS + ks * 8 + tig    ];
            unsigned a1 = Ps[(rbase + gid + 8) * FS + ks * 8 + tig    ];
            unsigned a2 = Ps[(rbase + gid    ) * FS + ks * 8 + tig + 4];
            unsigned a3 = Ps[(rbase + gid + 8) * FS + ks * 8 + tig + 4];
            #pragma unroll
            for (int nt = 0; nt < 8; nt++) {
                unsigned b0 = Vs[(ks * 8 + tig    ) * FS + nt * 8 + gid];
                unsigned b1 = Vs[(ks * 8 + tig + 4) * FS + nt * 8 + gid];
                mma_tf32(o[nt], a0, a1, a2, a3, b0, b1);
            }
        }
    }

    // epilogue: normalize, write [B,T,D]
    float inv_lo = 1.0f / l_lo;
    float inv_hi = 1.0f / l_hi;
    float* out_lo = out + (size_t)(b * TT + q0 + rbase + gid    ) * DD + h * HD;
    float* out_hi = out + (size_t)(b * TT + q0 + rbase + gid + 8) * DD + h * HD;
    #pragma unroll
    for (int nt = 0; nt < 8; nt++) {
        int cc = nt * 8 + tig * 2;
        *(float2*)(out_lo + cc) = make_float2(o[nt][0] * inv_lo, o[nt][1] * inv_lo);
        *(float2*)(out_hi + cc) = make_float2(o[nt][2] * inv_hi, o[nt][3] * inv_hi);
    }
}

// ---------------------------------------------------------------------------
extern "C" void kernel_launch(void* const* d_in, const int* in_sizes, int n_in,
                              void* d_out, int out_size)
{
    const float* x     = (const float*)d_in[0]; // [B,T,D]
    const float* w_qkv = (const float*)d_in[1]; // [D,3D]
    const float* w_out = (const float*)d_in[2]; // [D,D]
    float* out = (float*)d_out;                 // [B,T,D]

    float *qkv, *att;
    cudaGetSymbolAddress((void**)&qkv, g_qkv);
    cudaGetSymbolAddress((void**)&att, g_att);

    cudaFuncSetAttribute(flash_mma, cudaFuncAttributeMaxDynamicSharedMemorySize,
                         FLASH2_SMEM);

    const int M = BB * TT; // 4096

    // 1. qkv = x @ w_qkv  (tf32 tensor cores)
    gemm_tf32<<<dim3((3 * DD) / GBN, M / GBM), 256>>>(x, w_qkv, qkv, M, 3 * DD, DD);
    // 2. RoPE on q,k in place
    rope_k<<<(M * 2 * HH * 32) / 256, 256>>>(qkv);
    // 3. causal flash attention (tensor cores) -> att [B,T,D]
    flash_mma<<<dim3(TT / 64, BB * HH), 128, FLASH2_SMEM>>>(qkv, att);
    // 4. out = att @ w_out  (tf32 tensor cores)
    gemm_tf32<<<dim3(DD / GBN, M / GBM), 256>>>(att, w_out, out, M, DD, DD);
}

// round 5
// speedup vs baseline: 2.9601x; 1.1615x over previous
#include <cuda_runtime.h>
#include <math.h>

// Problem constants
#define BB 2
#define TT 2048
#define DD 1024
#define HH 16
#define HD 64

// Scratch (device globals; no runtime allocation allowed)
__device__ float g_qkv[(size_t)BB * TT * 3 * DD]; // [B*T, 3D]  q|k|v
__device__ float g_att[(size_t)BB * TT * DD];     // [B*T, D]   att out (tf32-rounded)
__device__ float g_xr[(size_t)BB * TT * DD];      // x rounded to tf32
__device__ float g_wqkvr[(size_t)DD * 3 * DD];    // w_qkv rounded to tf32
__device__ float g_woutr[(size_t)DD * DD];        // w_out rounded to tf32

__device__ __forceinline__ unsigned f2tf32(float f) {
    unsigned r;
    asm("cvt.rna.tf32.f32 %0, %1;" : "=r"(r) : "f"(f));
    return r;
}

__device__ __forceinline__ void mma_tf32(float c[4], unsigned a0, unsigned a1,
                                         unsigned a2, unsigned a3,
                                         unsigned b0, unsigned b1) {
    asm volatile(
        "mma.sync.aligned.m16n8k8.row.col.f32.tf32.tf32.f32 "
        "{%0,%1,%2,%3}, {%4,%5,%6,%7}, {%8,%9}, {%0,%1,%2,%3};\n"
        : "+f"(c[0]), "+f"(c[1]), "+f"(c[2]), "+f"(c[3])
        : "r"(a0), "r"(a1), "r"(a2), "r"(a3), "r"(b0), "r"(b1));
}

__device__ __forceinline__ void cp_async16(void* smem_dst, const void* gmem_src) {
    unsigned saddr = (unsigned)__cvta_generic_to_shared(smem_dst);
    asm volatile("cp.async.cg.shared.global [%0], [%1], 16;\n"
                 :: "r"(saddr), "l"(gmem_src));
}
#define CP_COMMIT() asm volatile("cp.async.commit_group;\n" ::: "memory")
#define CP_WAIT1()  asm volatile("cp.async.wait_group 1;\n" ::: "memory")
#define CP_WAIT0()  asm volatile("cp.async.wait_group 0;\n" ::: "memory")

// ---------------------------------------------------------------------------
// Elementwise round-to-tf32 (values become exactly tf32-representable fp32).
// ---------------------------------------------------------------------------
__global__ __launch_bounds__(256) void tf32_round(const float* __restrict__ src,
                                                  float* __restrict__ dst, int n)
{
    int i = (blockIdx.x * blockDim.x + threadIdx.x) * 4;
    if (i >= n) return;
    float4 v = *(const float4*)(src + i);
    uint4 u = make_uint4(f2tf32(v.x), f2tf32(v.y), f2tf32(v.z), f2tf32(v.w));
    *(float4*)(dst + i) = make_float4(__uint_as_float(u.x), __uint_as_float(u.y),
                                      __uint_as_float(u.z), __uint_as_float(u.w));
}

// ---------------------------------------------------------------------------
// TF32 tensor-core GEMM, cp.async double-buffered.
// C[M,N] = A[M,K] @ B[K,N]; A,B must already be tf32-rounded fp32.
// Block tile 128x128x16, 256 threads (8 warps), warp tile 64x32.
// ---------------------------------------------------------------------------
#define GBM 128
#define GBN 128
#define GBK 16
#define AST 20    // As row stride in words (16B-aligned rows, conflict-free frags)
#define BST 132   // Bs row stride in words

__global__ __launch_bounds__(256, 2) void gemm_tf32(const float* __restrict__ A,
                                                    const float* __restrict__ B,
                                                    float* __restrict__ C,
                                                    int M, int N, int K)
{
    __shared__ float As[2][GBM * AST];
    __shared__ float Bs[2][GBK * BST];

    const int tid  = threadIdx.x;
    const int warp = tid >> 5;
    const int lane = tid & 31;
    const int wm   = warp >> 2;   // 0..1
    const int wn   = warp & 3;    // 0..3
    const int gid  = lane >> 2;   // 0..7
    const int tig  = lane & 3;    // 0..3

    const int cRow = blockIdx.y * GBM;
    const int cCol = blockIdx.x * GBN;

    const int aR = tid >> 2;        // 0..63 (also +64)
    const int aC = (tid & 3) * 4;   // 0,4,8,12
    const int bR = tid >> 5;        // 0..7 (also +8)
    const int bC = lane * 4;        // 0..124

    float c[4][4][4];
    #pragma unroll
    for (int mt = 0; mt < 4; mt++)
        #pragma unroll
        for (int nt = 0; nt < 4; nt++)
            #pragma unroll
            for (int r = 0; r < 4; r++) c[mt][nt][r] = 0.0f;

    const int ntiles = K / GBK;

    // prologue: stage 0
    {
        const float* a0 = A + (size_t)(cRow + aR) * K + aC;
        cp_async16(&As[0][aR * AST + aC], a0);
        cp_async16(&As[0][(aR + 64) * AST + aC], a0 + (size_t)64 * K);
        const float* b0 = B + (size_t)bR * N + cCol + bC;
        cp_async16(&Bs[0][bR * BST + bC], b0);
        cp_async16(&Bs[0][(bR + 8) * BST + bC], b0 + (size_t)8 * N);
        CP_COMMIT();
    }

    for (int t = 0; t < ntiles; t++) {
        const int cur = t & 1;
        if (t + 1 < ntiles) {
            const int nk = (t + 1) * GBK;
            const int nxt = cur ^ 1;
            const float* a0 = A + (size_t)(cRow + aR) * K + nk + aC;
            cp_async16(&As[nxt][aR * AST + aC], a0);
            cp_async16(&As[nxt][(aR + 64) * AST + aC], a0 + (size_t)64 * K);
            const float* b0 = B + (size_t)(nk + bR) * N + cCol + bC;
            cp_async16(&Bs[nxt][bR * BST + bC], b0);
            cp_async16(&Bs[nxt][(bR + 8) * BST + bC], b0 + (size_t)8 * N);
            CP_COMMIT();
            CP_WAIT1();
        } else {
            CP_WAIT0();
        }
        __syncthreads();

        const float* as = As[cur];
        const float* bs = Bs[cur];
        #pragma unroll
        for (int ks = 0; ks < GBK; ks += 8) {
            unsigned af[4][4], bf[4][2];
            #pragma unroll
            for (int mt = 0; mt < 4; mt++) {
                int row = wm * 64 + mt * 16;
                af[mt][0] = __float_as_uint(as[(row + gid    ) * AST + ks + tig    ]);
                af[mt][1] = __float_as_uint(as[(row + gid + 8) * AST + ks + tig    ]);
                af[mt][2] = __float_as_uint(as[(row + gid    ) * AST + ks + tig + 4]);
                af[mt][3] = __float_as_uint(as[(row + gid + 8) * AST + ks + tig + 4]);
            }
            #pragma unroll
            for (int nt = 0; nt < 4; nt++) {
                int col = wn * 32 + nt * 8;
                bf[nt][0] = __float_as_uint(bs[(ks + tig    ) * BST + col + gid]);
                bf[nt][1] = __float_as_uint(bs[(ks + tig + 4) * BST + col + gid]);
            }
            #pragma unroll
            for (int mt = 0; mt < 4; mt++)
                #pragma unroll
                for (int nt = 0; nt < 4; nt++)
                    mma_tf32(c[mt][nt], af[mt][0], af[mt][1], af[mt][2], af[mt][3],
                             bf[nt][0], bf[nt][1]);
        }
        __syncthreads();
    }

    #pragma unroll
    for (int mt = 0; mt < 4; mt++) {
        #pragma unroll
        for (int nt = 0; nt < 4; nt++) {
            int row = cRow + wm * 64 + mt * 16 + gid;
            int col = cCol + wn * 32 + nt * 8 + tig * 2;
            *(float2*)(C + (size_t)row * N + col) =
                make_float2(c[mt][nt][0], c[mt][nt][1]);
            *(float2*)(C + (size_t)(row + 8) * N + col) =
                make_float2(c[mt][nt][2], c[mt][nt][3]);
        }
    }
}

// ---------------------------------------------------------------------------
// RoPE applied in place to q and k halves of the qkv buffer.
// ---------------------------------------------------------------------------
__global__ __launch_bounds__(256) void rope_k(float* __restrict__ qkv)
{
    int idx = blockIdx.x * blockDim.x + threadIdx.x;
    int j     = idx & 31;
    int h     = (idx >> 5) & 15;
    int which = (idx >> 9) & 1;
    int bt    = idx >> 10;
    if (bt >= BB * TT) return;

    int t = bt & (TT - 1);
    float inv = powf(10000.0f, -(float)j * (1.0f / 32.0f));
    float ang = (float)t * inv;
    float s, c;
    sincosf(ang, &s, &c);

    float* base = qkv + (size_t)bt * (3 * DD) + which * DD + h * HD;
    float x1 = base[j];
    float x2 = base[j + 32];
    base[j]      = x1 * c - x2 * s;
    base[j + 32] = x2 * c + x1 * s;
}

// ---------------------------------------------------------------------------
// Causal flash attention on tensor cores (tf32 m16n8k8). Unchanged from R4
// except the epilogue emits tf32-rounded values (so the out-proj GEMM can
// consume them without converting).
// ---------------------------------------------------------------------------
#define FS 68
#define FLASH2_SMEM (3 * 64 * FS * 4)

__global__ __launch_bounds__(128) void flash_mma(const float* __restrict__ qkv,
                                                 float* __restrict__ out)
{
    extern __shared__ unsigned smu[];
    unsigned* Qs = smu;            // [64][FS]  (aliased with Ps)
    unsigned* Ps = smu;
    unsigned* Ks = smu + 64 * FS;
    unsigned* Vs = smu + 2 * 64 * FS;

    const int qt = blockIdx.x;
    const int bh = blockIdx.y;
    const int b  = bh >> 4;
    const int h  = bh & 15;
    const int tid  = threadIdx.x;
    const int warp = tid >> 5;
    const int lane = tid & 31;
    const int gid  = lane >> 2;
    const int tig  = lane & 3;
    const int rbase = warp * 16;
    const float scale = 0.125f;

    const int q0 = qt * 64;
    const float* qbase = qkv + ((size_t)(b * TT + q0)) * (3 * DD) + h * HD;

    for (int i = tid; i < 64 * 16; i += 128) {
        int r  = i >> 4;
        int c4 = (i & 15) * 4;
        float4 v = *(const float4*)(qbase + (size_t)r * (3 * DD) + c4);
        uint4 u = make_uint4(f2tf32(v.x), f2tf32(v.y), f2tf32(v.z), f2tf32(v.w));
        *(uint4*)&Qs[r * FS + c4] = u;
    }
    __syncthreads();

    unsigned qf[8][4];
    #pragma unroll
    for (int ks = 0; ks < 8; ks++) {
        qf[ks][0] = Qs[(rbase + gid    ) * FS + ks * 8 + tig    ];
        qf[ks][1] = Qs[(rbase + gid + 8) * FS + ks * 8 + tig    ];
        qf[ks][2] = Qs[(rbase + gid    ) * FS + ks * 8 + tig + 4];
        qf[ks][3] = Qs[(rbase + gid + 8) * FS + ks * 8 + tig + 4];
    }

    float o[8][4];
    #pragma unroll
    for (int nt = 0; nt < 8; nt++)
        #pragma unroll
        for (int r = 0; r < 4; r++) o[nt][r] = 0.0f;
    float m_lo = -INFINITY, m_hi = -INFINITY;
    float l_lo = 0.0f, l_hi = 0.0f;

    const int row_lo = q0 + rbase + gid;
    const int row_hi = row_lo + 8;

    for (int kt = 0; kt <= qt; kt++) {
        const int k0 = kt * 64;
        const float* kbase = qkv + ((size_t)(b * TT + k0)) * (3 * DD) + DD + h * HD;
        const float* vbase = qkv + ((size_t)(b * TT + k0)) * (3 * DD) + 2 * DD + h * HD;

        __syncthreads();
        for (int i = tid; i < 64 * 16; i += 128) {
            int r  = i >> 4;
            int c4 = (i & 15) * 4;
            float4 kv = *(const float4*)(kbase + (size_t)r * (3 * DD) + c4);
            float4 vv = *(const float4*)(vbase + (size_t)r * (3 * DD) + c4);
            *(uint4*)&Ks[r * FS + c4] =
                make_uint4(f2tf32(kv.x), f2tf32(kv.y), f2tf32(kv.z), f2tf32(kv.w));
            *(uint4*)&Vs[r * FS + c4] =
                make_uint4(f2tf32(vv.x), f2tf32(vv.y), f2tf32(vv.z), f2tf32(vv.w));
        }
        __syncthreads();

        float s[8][4];
        #pragma unroll
        for (int nt = 0; nt < 8; nt++)
            #pragma unroll
            for (int r = 0; r < 4; r++) s[nt][r] = 0.0f;

        #pragma unroll
        for (int ks = 0; ks < 8; ks++) {
            #pragma unroll
            for (int nt = 0; nt < 8; nt++) {
                unsigned b0 = Ks[(nt * 8 + gid) * FS + ks * 8 + tig    ];
                unsigned b1 = Ks[(nt * 8 + gid) * FS + ks * 8 + tig + 4];
                mma_tf32(s[nt], qf[ks][0], qf[ks][1], qf[ks][2], qf[ks][3], b0, b1);
            }
        }

        if (kt == qt) {
            #pragma unroll
            for (int nt = 0; nt < 8; nt++) {
                int c0 = k0 + nt * 8 + tig * 2;
                s[nt][0] = (c0     > row_lo) ? -INFINITY : s[nt][0] * scale;
                s[nt][1] = (c0 + 1 > row_lo) ? -INFINITY : s[nt][1] * scale;
                s[nt][2] = (c0     > row_hi) ? -INFINITY : s[nt][2] * scale;
                s[nt][3] = (c0 + 1 > row_hi) ? -INFINITY : s[nt][3] * scale;
            }
        } else {
            #pragma unroll
            for (int nt = 0; nt < 8; nt++)
                #pragma unroll
                for (int r = 0; r < 4; r++) s[nt][r] *= scale;
        }

        float mx_lo = -INFINITY, mx_hi = -INFINITY;
        #pragma unroll
        for (int nt = 0; nt < 8; nt++) {
            mx_lo = fmaxf(mx_lo, fmaxf(s[nt][0], s[nt][1]));
            mx_hi = fmaxf(mx_hi, fmaxf(s[nt][2], s[nt][3]));
        }
        #pragma unroll
        for (int off = 1; off <= 2; off <<= 1) {
            mx_lo = fmaxf(mx_lo, __shfl_xor_sync(0xffffffffu, mx_lo, off));
            mx_hi = fmaxf(mx_hi, __shfl_xor_sync(0xffffffffu, mx_hi, off));
        }

        float newm_lo = fmaxf(m_lo, mx_lo);
        float newm_hi = fmaxf(m_hi, mx_hi);
        float alpha_lo = __expf(m_lo - newm_lo);
        float alpha_hi = __expf(m_hi - newm_hi);

        float sum_lo = 0.0f, sum_hi = 0.0f;
        #pragma unroll
        for (int nt = 0; nt < 8; nt++) {
            s[nt][0] = __expf(s[nt][0] - newm_lo);
            s[nt][1] = __expf(s[nt][1] - newm_lo);
            s[nt][2] = __expf(s[nt][2] - newm_hi);
            s[nt][3] = __expf(s[nt][3] - newm_hi);
            sum_lo += s[nt][0] + s[nt][1];
            sum_hi += s[nt][2] + s[nt][3];
        }
        #pragma unroll
        for (int off = 1; off <= 2; off <<= 1) {
            sum_lo += __shfl_xor_sync(0xffffffffu, sum_lo, off);
            sum_hi += __shfl_xor_sync(0xffffffffu, sum_hi, off);
        }

        l_lo = l_lo * alpha_lo + sum_lo;
        l_hi = l_hi * alpha_hi + sum_hi;
        m_lo = newm_lo;
        m_hi = newm_hi;

        #pragma unroll
        for (int nt = 0; nt < 8; nt++) {
            o[nt][0] *= alpha_lo; o[nt][1] *= alpha_lo;
            o[nt][2] *= alpha_hi; o[nt][3] *= alpha_hi;
        }

        #pragma unroll
        for (int nt = 0; nt < 8; nt++) {
            int cc = nt * 8 + tig * 2;
            *(uint2*)&Ps[(rbase + gid    ) * FS + cc] =
                make_uint2(f2tf32(s[nt][0]), f2tf32(s[nt][1]));
            *(uint2*)&Ps[(rbase + gid + 8) * FS + cc] =
                make_uint2(f2tf32(s[nt][2]), f2tf32(s[nt][3]));
        }
        __syncwarp();

        #pragma unroll
        for (int ks = 0; ks < 8; ks++) {
            unsigned a0 = Ps[(rbase + gid    ) * FS + ks * 8 + tig    ];
            unsigned a1 = Ps[(rbase + gid + 8) * FS + ks * 8 + tig    ];
            unsigned a2 = Ps[(rbase + gid    ) * FS + ks * 8 + tig + 4];
            unsigned a3 = Ps[(rbase + gid + 8) * FS + ks * 8 + tig + 4];
            #pragma unroll
            for (int nt = 0; nt < 8; nt++) {
                unsigned b0 = Vs[(ks * 8 + tig    ) * FS + nt * 8 + gid];
                unsigned b1 = Vs[(ks * 8 + tig + 4) * FS + nt * 8 + gid];
                mma_tf32(o[nt], a0, a1, a2, a3, b0, b1);
            }
        }
    }

    // epilogue: normalize, round to tf32, write [B,T,D]
    float inv_lo = 1.0f / l_lo;
    float inv_hi = 1.0f / l_hi;
    float* out_lo = out + (size_t)(b * TT + q0 + rbase + gid    ) * DD + h * HD;
    float* out_hi = out + (size_t)(b * TT + q0 + rbase + gid + 8) * DD + h * HD;
    #pragma unroll
    for (int nt = 0; nt < 8; nt++) {
        int cc = nt * 8 + tig * 2;
        *(float2*)(out_lo + cc) =
            make_float2(__uint_as_float(f2tf32(o[nt][0] * inv_lo)),
                        __uint_as_float(f2tf32(o[nt][1] * inv_lo)));
        *(float2*)(out_hi + cc) =
            make_float2(__uint_as_float(f2tf32(o[nt][2] * inv_hi)),
                        __uint_as_float(f2tf32(o[nt][3] * inv_hi)));
    }
}

// ---------------------------------------------------------------------------
extern "C" void kernel_launch(void* const* d_in, const int* in_sizes, int n_in,
                              void* d_out, int out_size)
{
    const float* x     = (const float*)d_in[0]; // [B,T,D]
    const float* w_qkv = (const float*)d_in[1]; // [D,3D]
    const float* w_out = (const float*)d_in[2]; // [D,D]
    float* out = (float*)d_out;                 // [B,T,D]

    float *qkv, *att, *xr, *wqkvr, *woutr;
    cudaGetSymbolAddress((void**)&qkv, g_qkv);
    cudaGetSymbolAddress((void**)&att, g_att);
    cudaGetSymbolAddress((void**)&xr, g_xr);
    cudaGetSymbolAddress((void**)&wqkvr, g_wqkvr);
    cudaGetSymbolAddress((void**)&woutr, g_woutr);

    cudaFuncSetAttribute(flash_mma, cudaFuncAttributeMaxDynamicSharedMemorySize,
                         FLASH2_SMEM);

    const int M = BB * TT; // 4096
    const int nx = M * DD, nwq = DD * 3 * DD, nwo = DD * DD;

    // 0. round GEMM inputs to tf32-representable fp32
    tf32_round<<<(nx  / 4 + 255) / 256, 256>>>(x, xr, nx);
    tf32_round<<<(nwq / 4 + 255) / 256, 256>>>(w_qkv, wqkvr, nwq);
    tf32_round<<<(nwo / 4 + 255) / 256, 256>>>(w_out, woutr, nwo);

    // 1. qkv = x @ w_qkv  (tf32 tensor cores, cp.async pipelined)
    gemm_tf32<<<dim3((3 * DD) / GBN, M / GBM), 256>>>(xr, wqkvr, qkv, M, 3 * DD, DD);
    // 2. RoPE on q,k in place
    rope_k<<<(M * 2 * HH * 32) / 256, 256>>>(qkv);
    // 3. causal flash attention (tensor cores) -> att (tf32-rounded)
    flash_mma<<<dim3(TT / 64, BB * HH), 128, FLASH2_SMEM>>>(qkv, att);
    // 4. out = att @ w_out  (tf32 tensor cores)
    gemm_tf32<<<dim3(DD / GBN, M / GBM), 256>>>(att, woutr, out, M, DD, DD);
}

// round 6
// speedup vs baseline: 3.0234x; 1.0214x over previous
#include <cuda_runtime.h>
#include <math.h>

// Problem constants
#define BB 2
#define TT 2048
#define DD 1024
#define HH 16
#define HD 64

// Scratch (device globals; no runtime allocation allowed)
__device__ float g_qkv[(size_t)BB * TT * 3 * DD]; // [B*T, 3D]  q|k|v
__device__ float g_att[(size_t)BB * TT * DD];     // [B*T, D]   att out (tf32-rounded)
__device__ float g_xr[(size_t)BB * TT * DD];      // x rounded to tf32
__device__ float g_wqkvr[(size_t)DD * 3 * DD];    // w_qkv rounded to tf32
__device__ float g_woutr[(size_t)DD * DD];        // w_out rounded to tf32

__device__ __forceinline__ unsigned f2tf32(float f) {
    unsigned r;
    asm("cvt.rna.tf32.f32 %0, %1;" : "=r"(r) : "f"(f));
    return r;
}

__device__ __forceinline__ void mma_tf32(float c[4], unsigned a0, unsigned a1,
                                         unsigned a2, unsigned a3,
                                         unsigned b0, unsigned b1) {
    asm volatile(
        "mma.sync.aligned.m16n8k8.row.col.f32.tf32.tf32.f32 "
        "{%0,%1,%2,%3}, {%4,%5,%6,%7}, {%8,%9}, {%0,%1,%2,%3};\n"
        : "+f"(c[0]), "+f"(c[1]), "+f"(c[2]), "+f"(c[3])
        : "r"(a0), "r"(a1), "r"(a2), "r"(a3), "r"(b0), "r"(b1));
}

__device__ __forceinline__ void cp_async16(void* smem_dst, const void* gmem_src) {
    unsigned saddr = (unsigned)__cvta_generic_to_shared(smem_dst);
    asm volatile("cp.async.cg.shared.global [%0], [%1], 16;\n"
                 :: "r"(saddr), "l"(gmem_src));
}
#define CP_COMMIT() asm volatile("cp.async.commit_group;\n" ::: "memory")
#define CP_WAIT1()  asm volatile("cp.async.wait_group 1;\n" ::: "memory")

// ---------------------------------------------------------------------------
// Elementwise round-to-tf32 (values become exactly tf32-representable fp32).
// ---------------------------------------------------------------------------
__global__ __launch_bounds__(256) void tf32_round(const float* __restrict__ src,
                                                  float* __restrict__ dst, int n)
{
    int i = (blockIdx.x * blockDim.x + threadIdx.x) * 4;
    if (i >= n) return;
    float4 v = *(const float4*)(src + i);
    uint4 u = make_uint4(f2tf32(v.x), f2tf32(v.y), f2tf32(v.z), f2tf32(v.w));
    *(float4*)(dst + i) = make_float4(__uint_as_float(u.x), __uint_as_float(u.y),
                                      __uint_as_float(u.z), __uint_as_float(u.w));
}

// ---------------------------------------------------------------------------
// TF32 tensor-core GEMM, 3-stage cp.async pipeline.
// C[M,N] = A[M,K] @ B[K,N]; A,B must already be tf32-rounded fp32.
// Block tile 128x128x16, 256 threads (8 warps), warp tile 64x32.
// Dynamic smem: 3 stages of (As 128x20 + Bs 16x132) floats = 56064 B.
// ---------------------------------------------------------------------------
#define GBM 128
#define GBN 128
#define GBK 16
#define AST 20
#define BST 132
#define A_STAGE (GBM * AST)
#define B_STAGE (GBK * BST)
#define GEMM_SMEM (3 * (A_STAGE + B_STAGE) * 4)

__global__ __launch_bounds__(256, 2) void gemm_tf32(const float* __restrict__ A,
                                                    const float* __restrict__ B,
                                                    float* __restrict__ C,
                                                    int M, int N, int K)
{
    extern __shared__ float gsm[];
    float* Asm = gsm;                 // 3 stages
    float* Bsm = gsm + 3 * A_STAGE;   // 3 stages

    const int tid  = threadIdx.x;
    const int warp = tid >> 5;
    const int lane = tid & 31;
    const int wm   = warp >> 2;   // 0..1
    const int wn   = warp & 3;    // 0..3
    const int gid  = lane >> 2;   // 0..7
    const int tig  = lane & 3;    // 0..3

    const int cRow = blockIdx.y * GBM;
    const int cCol = blockIdx.x * GBN;

    const int aR = tid >> 2;        // 0..63 (also +64)
    const int aC = (tid & 3) * 4;   // 0,4,8,12
    const int bR = tid >> 5;        // 0..7 (also +8)
    const int bC = lane * 4;        // 0..124

    const float* aG = A + (size_t)(cRow + aR) * K + aC;
    const float* bG = B + (size_t)bR * N + cCol + bC;

    float c[4][4][4];
    #pragma unroll
    for (int mt = 0; mt < 4; mt++)
        #pragma unroll
        for (int nt = 0; nt < 4; nt++)
            #pragma unroll
            for (int r = 0; r < 4; r++) c[mt][nt][r] = 0.0f;

    const int ntiles = K / GBK;

    // prologue: stage tiles 0 and 1
    #pragma unroll
    for (int t = 0; t < 2; t++) {
        float* as = Asm + t * A_STAGE;
        float* bs = Bsm + t * B_STAGE;
        cp_async16(&as[aR * AST + aC], aG + t * GBK);
        cp_async16(&as[(aR + 64) * AST + aC], aG + (size_t)64 * K + t * GBK);
        cp_async16(&bs[bR * BST + bC], bG + (size_t)t * GBK * N);
        cp_async16(&bs[(bR + 8) * BST + bC], bG + (size_t)(t * GBK + 8) * N);
        CP_COMMIT();
    }

    int slot = 0;
    for (int t = 0; t < ntiles; t++) {
        CP_WAIT1();        // tile t's copies complete (t+1 still in flight)
        __syncthreads();   // visible to all; slot being refilled is drained

        // issue prefetch for tile t+2 into the slot tile t-1 used
        if (t + 2 < ntiles) {
            int ps = slot + 2; if (ps >= 3) ps -= 3;
            int nk = (t + 2) * GBK;
            float* as = Asm + ps * A_STAGE;
            float* bs = Bsm + ps * B_STAGE;
            cp_async16(&as[aR * AST + aC], aG + nk);
            cp_async16(&as[(aR + 64) * AST + aC], aG + (size_t)64 * K + nk);
            cp_async16(&bs[bR * BST + bC], bG + (size_t)nk * N);
            cp_async16(&bs[(bR + 8) * BST + bC], bG + (size_t)(nk + 8) * N);
        }
        CP_COMMIT();       // commit (possibly empty) to keep group accounting

        const float* as = Asm + slot * A_STAGE;
        const float* bs = Bsm + slot * B_STAGE;
        #pragma unroll
        for (int ks = 0; ks < GBK; ks += 8) {
            unsigned af[4][4], bf[4][2];
            #pragma unroll
            for (int mt = 0; mt < 4; mt++) {
                int row = wm * 64 + mt * 16;
                af[mt][0] = __float_as_uint(as[(row + gid    ) * AST + ks + tig    ]);
                af[mt][1] = __float_as_uint(as[(row + gid + 8) * AST + ks + tig    ]);
                af[mt][2] = __float_as_uint(as[(row + gid    ) * AST + ks + tig + 4]);
                af[mt][3] = __float_as_uint(as[(row + gid + 8) * AST + ks + tig + 4]);
            }
            #pragma unroll
            for (int nt = 0; nt < 4; nt++) {
                int col = wn * 32 + nt * 8;
                bf[nt][0] = __float_as_uint(bs[(ks + tig    ) * BST + col + gid]);
                bf[nt][1] = __float_as_uint(bs[(ks + tig + 4) * BST + col + gid]);
            }
            #pragma unroll
            for (int mt = 0; mt < 4; mt++)
                #pragma unroll
                for (int nt = 0; nt < 4; nt++)
                    mma_tf32(c[mt][nt], af[mt][0], af[mt][1], af[mt][2], af[mt][3],
                             bf[nt][0], bf[nt][1]);
        }
        if (++slot >= 3) slot = 0;
    }

    #pragma unroll
    for (int mt = 0; mt < 4; mt++) {
        #pragma unroll
        for (int nt = 0; nt < 4; nt++) {
            int row = cRow + wm * 64 + mt * 16 + gid;
            int col = cCol + wn * 32 + nt * 8 + tig * 2;
            *(float2*)(C + (size_t)row * N + col) =
                make_float2(c[mt][nt][0], c[mt][nt][1]);
            *(float2*)(C + (size_t)(row + 8) * N + col) =
                make_float2(c[mt][nt][2], c[mt][nt][3]);
        }
    }
}

// ---------------------------------------------------------------------------
// RoPE applied in place to q and k halves of the qkv buffer.
// ---------------------------------------------------------------------------
__global__ __launch_bounds__(256) void rope_k(float* __restrict__ qkv)
{
    int idx = blockIdx.x * blockDim.x + threadIdx.x;
    int j     = idx & 31;
    int h     = (idx >> 5) & 15;
    int which = (idx >> 9) & 1;
    int bt    = idx >> 10;
    if (bt >= BB * TT) return;

    int t = bt & (TT - 1);
    float inv = powf(10000.0f, -(float)j * (1.0f / 32.0f));
    float ang = (float)t * inv;
    float s, c;
    sincosf(ang, &s, &c);

    float* base = qkv + (size_t)bt * (3 * DD) + which * DD + h * HD;
    float x1 = base[j];
    float x2 = base[j + 32];
    base[j]      = x1 * c - x2 * s;
    base[j + 32] = x2 * c + x1 * s;
}

// ---------------------------------------------------------------------------
// Causal flash attention on tensor cores (tf32 m16n8k8).
// Q is pre-scaled by 1/sqrt(d)=2^-3 in the prologue (exact), removing the
// per-tile scale multiplies.
// ---------------------------------------------------------------------------
#define FS 68
#define FLASH2_SMEM (3 * 64 * FS * 4)

__global__ __launch_bounds__(128) void flash_mma(const float* __restrict__ qkv,
                                                 float* __restrict__ out)
{
    extern __shared__ unsigned smu[];
    unsigned* Qs = smu;            // [64][FS]  (aliased with Ps)
    unsigned* Ps = smu;
    unsigned* Ks = smu + 64 * FS;
    unsigned* Vs = smu + 2 * 64 * FS;

    const int qt = blockIdx.x;
    const int bh = blockIdx.y;
    const int b  = bh >> 4;
    const int h  = bh & 15;
    const int tid  = threadIdx.x;
    const int warp = tid >> 5;
    const int lane = tid & 31;
    const int gid  = lane >> 2;
    const int tig  = lane & 3;
    const int rbase = warp * 16;

    const int q0 = qt * 64;
    const float* qbase = qkv + ((size_t)(b * TT + q0)) * (3 * DD) + h * HD;

    for (int i = tid; i < 64 * 16; i += 128) {
        int r  = i >> 4;
        int c4 = (i & 15) * 4;
        float4 v = *(const float4*)(qbase + (size_t)r * (3 * DD) + c4);
        uint4 u = make_uint4(f2tf32(v.x * 0.125f), f2tf32(v.y * 0.125f),
                             f2tf32(v.z * 0.125f), f2tf32(v.w * 0.125f));
        *(uint4*)&Qs[r * FS + c4] = u;
    }
    __syncthreads();

    unsigned qf[8][4];
    #pragma unroll
    for (int ks = 0; ks < 8; ks++) {
        qf[ks][0] = Qs[(rbase + gid    ) * FS + ks * 8 + tig    ];
        qf[ks][1] = Qs[(rbase + gid + 8) * FS + ks * 8 + tig    ];
        qf[ks][2] = Qs[(rbase + gid    ) * FS + ks * 8 + tig + 4];
        qf[ks][3] = Qs[(rbase + gid + 8) * FS + ks * 8 + tig + 4];
    }

    float o[8][4];
    #pragma unroll
    for (int nt = 0; nt < 8; nt++)
        #pragma unroll
        for (int r = 0; r < 4; r++) o[nt][r] = 0.0f;
    float m_lo = -INFINITY, m_hi = -INFINITY;
    float l_lo = 0.0f, l_hi = 0.0f;

    const int row_lo = q0 + rbase + gid;
    const int row_hi = row_lo + 8;

    for (int kt = 0; kt <= qt; kt++) {
        const int k0 = kt * 64;
        const float* kbase = qkv + ((size_t)(b * TT + k0)) * (3 * DD) + DD + h * HD;
        const float* vbase = qkv + ((size_t)(b * TT + k0)) * (3 * DD) + 2 * DD + h * HD;

        __syncthreads();
        for (int i = tid; i < 64 * 16; i += 128) {
            int r  = i >> 4;
            int c4 = (i & 15) * 4;
            float4 kv = *(const float4*)(kbase + (size_t)r * (3 * DD) + c4);
            float4 vv = *(const float4*)(vbase + (size_t)r * (3 * DD) + c4);
            *(uint4*)&Ks[r * FS + c4] =
                make_uint4(f2tf32(kv.x), f2tf32(kv.y), f2tf32(kv.z), f2tf32(kv.w));
            *(uint4*)&Vs[r * FS + c4] =
                make_uint4(f2tf32(vv.x), f2tf32(vv.y), f2tf32(vv.z), f2tf32(vv.w));
        }
        __syncthreads();

        float s[8][4];
        #pragma unroll
        for (int nt = 0; nt < 8; nt++)
            #pragma unroll
            for (int r = 0; r < 4; r++) s[nt][r] = 0.0f;

        #pragma unroll
        for (int ks = 0; ks < 8; ks++) {
            #pragma unroll
            for (int nt = 0; nt < 8; nt++) {
                unsigned b0 = Ks[(nt * 8 + gid) * FS + ks * 8 + tig    ];
                unsigned b1 = Ks[(nt * 8 + gid) * FS + ks * 8 + tig + 4];
                mma_tf32(s[nt], qf[ks][0], qf[ks][1], qf[ks][2], qf[ks][3], b0, b1);
            }
        }

        if (kt == qt) {
            #pragma unroll
            for (int nt = 0; nt < 8; nt++) {
                int c0 = k0 + nt * 8 + tig * 2;
                if (c0     > row_lo) s[nt][0] = -INFINITY;
                if (c0 + 1 > row_lo) s[nt][1] = -INFINITY;
                if (c0     > row_hi) s[nt][2] = -INFINITY;
                if (c0 + 1 > row_hi) s[nt][3] = -INFINITY;
            }
        }

        float mx_lo = -INFINITY, mx_hi = -INFINITY;
        #pragma unroll
        for (int nt = 0; nt < 8; nt++) {
            mx_lo = fmaxf(mx_lo, fmaxf(s[nt][0], s[nt][1]));
            mx_hi = fmaxf(mx_hi, fmaxf(s[nt][2], s[nt][3]));
        }
        #pragma unroll
        for (int off = 1; off <= 2; off <<= 1) {
            mx_lo = fmaxf(mx_lo, __shfl_xor_sync(0xffffffffu, mx_lo, off));
            mx_hi = fmaxf(mx_hi, __shfl_xor_sync(0xffffffffu, mx_hi, off));
        }

        float newm_lo = fmaxf(m_lo, mx_lo);
        float newm_hi = fmaxf(m_hi, mx_hi);
        float alpha_lo = __expf(m_lo - newm_lo);
        float alpha_hi = __expf(m_hi - newm_hi);

        float sum_lo = 0.0f, sum_hi = 0.0f;
        #pragma unroll
        for (int nt = 0; nt < 8; nt++) {
            s[nt][0] = __expf(s[nt][0] - newm_lo);
            s[nt][1] = __expf(s[nt][1] - newm_lo);
            s[nt][2] = __expf(s[nt][2] - newm_hi);
            s[nt][3] = __expf(s[nt][3] - newm_hi);
            sum_lo += s[nt][0] + s[nt][1];
            sum_hi += s[nt][2] + s[nt][3];
        }
        #pragma unroll
        for (int off = 1; off <= 2; off <<= 1) {
            sum_lo += __shfl_xor_sync(0xffffffffu, sum_lo, off);
            sum_hi += __shfl_xor_sync(0xffffffffu, sum_hi, off);
        }

        l_lo = l_lo * alpha_lo + sum_lo;
        l_hi = l_hi * alpha_hi + sum_hi;
        m_lo = newm_lo;
        m_hi = newm_hi;

        #pragma unroll
        for (int nt = 0; nt < 8; nt++) {
            o[nt][0] *= alpha_lo; o[nt][1] *= alpha_lo;
            o[nt][2] *= alpha_hi; o[nt][3] *= alpha_hi;
        }

        #pragma unroll
        for (int nt = 0; nt < 8; nt++) {
            int cc = nt * 8 + tig * 2;
            *(uint2*)&Ps[(rbase + gid    ) * FS + cc] =
                make_uint2(f2tf32(s[nt][0]), f2tf32(s[nt][1]));
            *(uint2*)&Ps[(rbase + gid + 8) * FS + cc] =
                make_uint2(f2tf32(s[nt][2]), f2tf32(s[nt][3]));
        }
        __syncwarp();

        #pragma unroll
        for (int ks = 0; ks < 8; ks++) {
            unsigned a0 = Ps[(rbase + gid    ) * FS + ks * 8 + tig    ];
            unsigned a1 = Ps[(rbase + gid + 8) * FS + ks * 8 + tig    ];
            unsigned a2 = Ps[(rbase + gid    ) * FS + ks * 8 + tig + 4];
            unsigned a3 = Ps[(rbase + gid + 8) * FS + ks * 8 + tig + 4];
            #pragma unroll
            for (int nt = 0; nt < 8; nt++) {
                unsigned b0 = Vs[(ks * 8 + tig    ) * FS + nt * 8 + gid];
                unsigned b1 = Vs[(ks * 8 + tig + 4) * FS + nt * 8 + gid];
                mma_tf32(o[nt], a0, a1, a2, a3, b0, b1);
            }
        }
    }

    float inv_lo = 1.0f / l_lo;
    float inv_hi = 1.0f / l_hi;
    float* out_lo = out + (size_t)(b * TT + q0 + rbase + gid    ) * DD + h * HD;
    float* out_hi = out + (size_t)(b * TT + q0 + rbase + gid + 8) * DD + h * HD;
    #pragma unroll
    for (int nt = 0; nt < 8; nt++) {
        int cc = nt * 8 + tig * 2;
        *(float2*)(out_lo + cc) =
            make_float2(__uint_as_float(f2tf32(o[nt][0] * inv_lo)),
                        __uint_as_float(f2tf32(o[nt][1] * inv_lo)));
        *(float2*)(out_hi + cc) =
            make_float2(__uint_as_float(f2tf32(o[nt][2] * inv_hi)),
                        __uint_as_float(f2tf32(o[nt][3] * inv_hi)));
    }
}

// ---------------------------------------------------------------------------
extern "C" void kernel_launch(void* const* d_in, const int* in_sizes, int n_in,
                              void* d_out, int out_size)
{
    const float* x     = (const float*)d_in[0]; // [B,T,D]
    const float* w_qkv = (const float*)d_in[1]; // [D,3D]
    const float* w_out = (const float*)d_in[2]; // [D,D]
    float* out = (float*)d_out;                 // [B,T,D]

    float *qkv, *att, *xr, *wqkvr, *woutr;
    cudaGetSymbolAddress((void**)&qkv, g_qkv);
    cudaGetSymbolAddress((void**)&att, g_att);
    cudaGetSymbolAddress((void**)&xr, g_xr);
    cudaGetSymbolAddress((void**)&wqkvr, g_wqkvr);
    cudaGetSymbolAddress((void**)&woutr, g_woutr);

    cudaFuncSetAttribute(flash_mma, cudaFuncAttributeMaxDynamicSharedMemorySize,
                         FLASH2_SMEM);
    cudaFuncSetAttribute(gemm_tf32, cudaFuncAttributeMaxDynamicSharedMemorySize,
                         GEMM_SMEM);

    const int M = BB * TT; // 4096
    const int nx = M * DD, nwq = DD * 3 * DD, nwo = DD * DD;

    // 0. round GEMM inputs to tf32-representable fp32
    tf32_round<<<(nx  / 4 + 255) / 256, 256>>>(x, xr, nx);
    tf32_round<<<(nwq / 4 + 255) / 256, 256>>>(w_qkv, wqkvr, nwq);
    tf32_round<<<(nwo / 4 + 255) / 256, 256>>>(w_out, woutr, nwo);

    // 1. qkv = x @ w_qkv  (tf32 tensor cores, 3-stage cp.async)
    gemm_tf32<<<dim3((3 * DD) / GBN, M / GBM), 256, GEMM_SMEM>>>(xr, wqkvr, qkv,
                                                                 M, 3 * DD, DD);
    // 2. RoPE on q,k in place
    rope_k<<<(M * 2 * HH * 32) / 256, 256>>>(qkv);
    // 3. causal flash attention (tensor cores) -> att (tf32-rounded)
    flash_mma<<<dim3(TT / 64, BB * HH), 128, FLASH2_SMEM>>>(qkv, att);
    // 4. out = att @ w_out  (tf32 tensor cores)
    gemm_tf32<<<dim3(DD / GBN, M / GBM), 256, GEMM_SMEM>>>(att, woutr, out,
                                                           M, DD, DD);
}

// round 9
// speedup vs baseline: 5.8319x; 1.9289x over previous
#include <cuda_runtime.h>
#include <cuda_fp16.h>
#include <math.h>

// Problem constants
#define BB 2
#define TT 2048
#define DD 1024
#define HH 16
#define HD 64

// Scratch (device globals; no runtime allocation allowed)
__device__ float  g_qkv[(size_t)BB * TT * 3 * DD]; // [B*T, 3D] q|k|v fp32
__device__ __half g_atth[(size_t)BB * TT * DD];    // attention out, fp16
__device__ __half g_xh[(size_t)BB * TT * DD];      // x in fp16
__device__ __half g_wqh[(size_t)DD * 3 * DD];      // w_qkv fp16 [K][N]
__device__ __half g_woh[(size_t)DD * DD];          // w_out fp16 [K][N]

__device__ __forceinline__ unsigned pack2(float a, float b) {
    __half2 h = __floats2half2_rn(a, b);
    return *(unsigned*)&h;
}

__device__ __forceinline__ void mma_f16(float c[4], unsigned a0, unsigned a1,
                                        unsigned a2, unsigned a3,
                                        unsigned b0, unsigned b1) {
    asm volatile(
        "mma.sync.aligned.m16n8k16.row.col.f32.f16.f16.f32 "
        "{%0,%1,%2,%3}, {%4,%5,%6,%7}, {%8,%9}, {%0,%1,%2,%3};\n"
        : "+f"(c[0]), "+f"(c[1]), "+f"(c[2]), "+f"(c[3])
        : "r"(a0), "r"(a1), "r"(a2), "r"(a3), "r"(b0), "r"(b1));
}

__device__ __forceinline__ void ldsm_x4(unsigned& r0, unsigned& r1,
                                        unsigned& r2, unsigned& r3, unsigned a) {
    asm volatile("ldmatrix.sync.aligned.m8n8.x4.shared.b16 {%0,%1,%2,%3}, [%4];"
                 : "=r"(r0), "=r"(r1), "=r"(r2), "=r"(r3) : "r"(a));
}
__device__ __forceinline__ void ldsm_x4_t(unsigned& r0, unsigned& r1,
                                          unsigned& r2, unsigned& r3, unsigned a) {
    asm volatile("ldmatrix.sync.aligned.m8n8.x4.trans.shared.b16 {%0,%1,%2,%3}, [%4];"
                 : "=r"(r0), "=r"(r1), "=r"(r2), "=r"(r3) : "r"(a));
}

__device__ __forceinline__ void cp_async16_s(unsigned saddr, const void* g) {
    asm volatile("cp.async.cg.shared.global [%0], [%1], 16;\n"
                 :: "r"(saddr), "l"(g));
}
#define CP_COMMIT() asm volatile("cp.async.commit_group;\n" ::: "memory")
#define CP_WAIT1()  asm volatile("cp.async.wait_group 1;\n" ::: "memory")
#define CP_WAIT0()  asm volatile("cp.async.wait_group 0;\n" ::: "memory")

// ---------------------------------------------------------------------------
// fp32 -> fp16 elementwise (8 per thread)
// ---------------------------------------------------------------------------
__global__ __launch_bounds__(256) void f2h_k(const float* __restrict__ src,
                                             __half* __restrict__ dst, int n)
{
    int i = (blockIdx.x * blockDim.x + threadIdx.x) * 8;
    if (i >= n) return;
    float4 v0 = *(const float4*)(src + i);
    float4 v1 = *(const float4*)(src + i + 4);
    uint4 u = make_uint4(pack2(v0.x, v0.y), pack2(v0.z, v0.w),
                         pack2(v1.x, v1.y), pack2(v1.z, v1.w));
    *(uint4*)(dst + i) = u;
}

// ---------------------------------------------------------------------------
// fp16 tensor-core GEMM: C[M,N] = A[M,K] @ B[K,N] (fp32 out).
// A fp16 row-major; B fp16 row-major (consumed via ldmatrix.trans).
// Block 128x128x32(halves), 256 threads, warp tile 64x32, mma m16n8k16.
// 2-stage cp.async. Smem: A rows 64B data pad to 80B; B rows 256B pad 272B.
// ---------------------------------------------------------------------------
#define BKH 32
#define A_ST 80
#define B_ST 272
#define A_STAGEB (128 * A_ST)            // 10240
#define B_STAGEB (BKH * B_ST)            // 8704
#define STAGEB (A_STAGEB + B_STAGEB)
#define GH_SMEM (2 * STAGEB)             // 37888

__global__ __launch_bounds__(256, 2) void gemm_f16(const __half* __restrict__ A,
                                                   const __half* __restrict__ B,
                                                   float* __restrict__ C,
                                                   int M, int N, int K)
{
    extern __shared__ unsigned char hsm[];
    const unsigned sbase = (unsigned)__cvta_generic_to_shared(hsm);

    const int tid  = threadIdx.x;
    const int warp = tid >> 5;
    const int lane = tid & 31;
    const int wm   = warp >> 2;   // 0..1
    const int wn   = warp & 3;    // 0..3
    const int gid  = lane >> 2;
    const int tig  = lane & 3;
    const int sel  = lane >> 3;   // 0..3 (ldmatrix matrix select)
    const int lrow = lane & 7;

    const int cRow = blockIdx.y * 128;
    const int cCol = blockIdx.x * 128;

    // cp.async assignments: A 512 chunks of 16B, B 512 chunks of 16B
    const int arI = tid >> 1;               // with +128: rows 0..127 twice? no:
    // A: i in [0,512): r=i>>2, c=i&3  (two per thread: i=tid, i=tid+256)
    // B: i in [0,512): k=i>>4, c=i&15

    float c[4][4][4];
    #pragma unroll
    for (int mt = 0; mt < 4; mt++)
        #pragma unroll
        for (int nt = 0; nt < 4; nt++)
            #pragma unroll
            for (int r = 0; r < 4; r++) c[mt][nt][r] = 0.0f;

    const int ntiles = K / BKH;
    (void)arI;

    auto load_stage = [&](int t) {
        unsigned bufA = sbase + (t & 1) * STAGEB;
        unsigned bufB = bufA + A_STAGEB;
        int k0 = t * BKH;
        #pragma unroll
        for (int j = 0; j < 2; j++) {
            int i = tid + j * 256;
            int r = i >> 2, cc = i & 3;
            cp_async16_s(bufA + r * A_ST + cc * 16,
                         A + (size_t)(cRow + r) * K + k0 + cc * 8);
            int k = i >> 4, bc = i & 15;
            cp_async16_s(bufB + k * B_ST + bc * 16,
                         B + (size_t)(k0 + k) * N + cCol + bc * 8);
        }
        CP_COMMIT();
    };

    load_stage(0);

    for (int t = 0; t < ntiles; t++) {
        if (t + 1 < ntiles) {
            load_stage(t + 1);
            CP_WAIT1();
        } else {
            CP_WAIT0();
        }
        __syncthreads();

        unsigned bufA = sbase + (t & 1) * STAGEB;
        unsigned bufB = bufA + A_STAGEB;

        #pragma unroll
        for (int s = 0; s < 2; s++) {
            unsigned af[4][4];
            #pragma unroll
            for (int mt = 0; mt < 4; mt++) {
                int row = wm * 64 + mt * 16 + (sel & 1) * 8 + lrow;
                ldsm_x4(af[mt][0], af[mt][1], af[mt][2], af[mt][3],
                        bufA + row * A_ST + s * 32 + (sel >> 1) * 16);
            }
            unsigned bf[4][2];
            #pragma unroll
            for (int p = 0; p < 2; p++) {
                int krow = s * 16 + (sel & 1) * 8 + lrow;
                int ncol = wn * 32 + (p * 2 + (sel >> 1)) * 8;
                unsigned r0, r1, r2, r3;
                ldsm_x4_t(r0, r1, r2, r3, bufB + krow * B_ST + ncol * 2);
                bf[p * 2][0] = r0; bf[p * 2][1] = r1;
                bf[p * 2 + 1][0] = r2; bf[p * 2 + 1][1] = r3;
            }
            #pragma unroll
            for (int mt = 0; mt < 4; mt++)
                #pragma unroll
                for (int nt = 0; nt < 4; nt++)
                    mma_f16(c[mt][nt], af[mt][0], af[mt][1], af[mt][2], af[mt][3],
                            bf[nt][0], bf[nt][1]);
        }
        __syncthreads();
    }

    #pragma unroll
    for (int mt = 0; mt < 4; mt++) {
        #pragma unroll
        for (int nt = 0; nt < 4; nt++) {
            int row = cRow + wm * 64 + mt * 16 + gid;
            int col = cCol + wn * 32 + nt * 8 + tig * 2;
            *(float2*)(C + (size_t)row * N + col) =
                make_float2(c[mt][nt][0], c[mt][nt][1]);
            *(float2*)(C + (size_t)(row + 8) * N + col) =
                make_float2(c[mt][nt][2], c[mt][nt][3]);
        }
    }
}

// ---------------------------------------------------------------------------
// RoPE applied in place to q and k halves of the qkv buffer (fp32).
// ---------------------------------------------------------------------------
__global__ __launch_bounds__(256) void rope_k(float* __restrict__ qkv)
{
    int idx = blockIdx.x * blockDim.x + threadIdx.x;
    int j     = idx & 31;
    int h     = (idx >> 5) & 15;
    int which = (idx >> 9) & 1;
    int bt    = idx >> 10;
    if (bt >= BB * TT) return;

    int t = bt & (TT - 1);
    float inv = powf(10000.0f, -(float)j * (1.0f / 32.0f));
    float ang = (float)t * inv;
    float s, c;
    sincosf(ang, &s, &c);

    float* base = qkv + (size_t)bt * (3 * DD) + which * DD + h * HD;
    float x1 = base[j];
    float x2 = base[j + 32];
    base[j]      = x1 * c - x2 * s;
    base[j + 32] = x2 * c + x1 * s;
}

// ---------------------------------------------------------------------------
// Causal flash attention, fp16 mma m16n8k16.
// Block = 64 q-rows of one (b,h), 128 threads / 4 warps; warp owns 16 q-rows.
// Q/K/V fp16 in smem (row stride 72 halves = 144B, conflict-free ldmatrix).
// Q pre-scaled by 1/8. P stays in registers (S C-frags repack to PV A-frags).
// Output written as fp16 (feeds gemm_f16 directly).
// ---------------------------------------------------------------------------
#define FST 72
#define FSTB 144
#define FLASH_H_SMEM (3 * 64 * FSTB)   // 27648

__global__ __launch_bounds__(128) void flash_f16(const float* __restrict__ qkv,
                                                 __half* __restrict__ out)
{
    extern __shared__ __half fsm[];
    __half* Qs = fsm;
    __half* Ks = fsm + 64 * FST;
    __half* Vs = fsm + 128 * FST;
    const unsigned qs = (unsigned)__cvta_generic_to_shared(Qs);
    const unsigned ks = (unsigned)__cvta_generic_to_shared(Ks);
    const unsigned vs = (unsigned)__cvta_generic_to_shared(Vs);

    const int qt = blockIdx.x;
    const int bh = blockIdx.y;
    const int b  = bh >> 4;
    const int h  = bh & 15;
    const int tid  = threadIdx.x;
    const int warp = tid >> 5;
    const int lane = tid & 31;
    const int gid  = lane >> 2;
    const int tig  = lane & 3;
    const int sel  = lane >> 3;
    const int lrow = lane & 7;
    const int rbase = warp * 16;

    const int q0 = qt * 64;
    const float* qg = qkv + ((size_t)(b * TT + q0)) * (3 * DD) + h * HD;

    // Q -> smem fp16, scaled by 1/8
    for (int i = tid; i < 512; i += 128) {
        int r = i >> 3, cc = i & 7;
        const float* p = qg + (size_t)r * (3 * DD) + cc * 8;
        float4 v0 = *(const float4*)p;
        float4 v1 = *(const float4*)(p + 4);
        uint4 u = make_uint4(pack2(v0.x * 0.125f, v0.y * 0.125f),
                             pack2(v0.z * 0.125f, v0.w * 0.125f),
                             pack2(v1.x * 0.125f, v1.y * 0.125f),
                             pack2(v1.z * 0.125f, v1.w * 0.125f));
        *(uint4*)((char*)Qs + r * FSTB + cc * 16) = u;
    }
    __syncthreads();

    // Q fragments -> registers (4 k16 chunks over d=64)
    unsigned qf[4][4];
    #pragma unroll
    for (int s = 0; s < 4; s++) {
        int row = rbase + (sel & 1) * 8 + lrow;
        ldsm_x4(qf[s][0], qf[s][1], qf[s][2], qf[s][3],
                qs + row * FSTB + s * 32 + (sel >> 1) * 16);
    }

    float o[8][4];
    #pragma unroll
    for (int nt = 0; nt < 8; nt++)
        #pragma unroll
        for (int r = 0; r < 4; r++) o[nt][r] = 0.0f;
    float m_lo = -INFINITY, m_hi = -INFINITY;
    float l_lo = 0.0f, l_hi = 0.0f;

    const int row_lo = q0 + rbase + gid;
    const int row_hi = row_lo + 8;

    for (int kt = 0; kt <= qt; kt++) {
        const int k0 = kt * 64;
        const float* kg = qkv + ((size_t)(b * TT + k0)) * (3 * DD) + DD + h * HD;
        const float* vg = qkv + ((size_t)(b * TT + k0)) * (3 * DD) + 2 * DD + h * HD;

        __syncthreads();
        for (int i = tid; i < 512; i += 128) {
            int r = i >> 3, cc = i & 7;
            const float* pk = kg + (size_t)r * (3 * DD) + cc * 8;
            const float* pv = vg + (size_t)r * (3 * DD) + cc * 8;
            float4 k0v = *(const float4*)pk;
            float4 k1v = *(const float4*)(pk + 4);
            float4 v0v = *(const float4*)pv;
            float4 v1v = *(const float4*)(pv + 4);
            *(uint4*)((char*)Ks + r * FSTB + cc * 16) =
                make_uint4(pack2(k0v.x, k0v.y), pack2(k0v.z, k0v.w),
                           pack2(k1v.x, k1v.y), pack2(k1v.z, k1v.w));
            *(uint4*)((char*)Vs + r * FSTB + cc * 16) =
                make_uint4(pack2(v0v.x, v0v.y), pack2(v0v.z, v0v.w),
                           pack2(v1v.x, v1v.y), pack2(v1v.z, v1v.w));
        }
        __syncthreads();

        // S = Q K^T
        float sc[8][4];
        #pragma unroll
        for (int nt = 0; nt < 8; nt++)
            #pragma unroll
            for (int r = 0; r < 4; r++) sc[nt][r] = 0.0f;

        #pragma unroll
        for (int s = 0; s < 4; s++) {
            unsigned kb[8][2];
            #pragma unroll
            for (int p = 0; p < 4; p++) {
                int trow = (p * 2 + (sel >> 1)) * 8 + lrow;
                unsigned r0, r1, r2, r3;
                ldsm_x4(r0, r1, r2, r3,
                        ks + trow * FSTB + s * 32 + (sel & 1) * 16);
                kb[p * 2][0] = r0; kb[p * 2][1] = r1;
                kb[p * 2 + 1][0] = r2; kb[p * 2 + 1][1] = r3;
            }
            #pragma unroll
            for (int nt = 0; nt < 8; nt++)
                mma_f16(sc[nt], qf[s][0], qf[s][1], qf[s][2], qf[s][3],
                        kb[nt][0], kb[nt][1]);
        }

        if (kt == qt) {
            #pragma unroll
            for (int nt = 0; nt < 8; nt++) {
                int c0 = k0 + nt * 8 + tig * 2;
                if (c0     > row_lo) sc[nt][0] = -INFINITY;
                if (c0 + 1 > row_lo) sc[nt][1] = -INFINITY;
                if (c0     > row_hi) sc[nt][2] = -INFINITY;
                if (c0 + 1 > row_hi) sc[nt][3] = -INFINITY;
            }
        }

        float mx_lo = -INFINITY, mx_hi = -INFINITY;
        #pragma unroll
        for (int nt = 0; nt < 8; nt++) {
            mx_lo = fmaxf(mx_lo, fmaxf(sc[nt][0], sc[nt][1]));
            mx_hi = fmaxf(mx_hi, fmaxf(sc[nt][2], sc[nt][3]));
        }
        #pragma unroll
        for (int off = 1; off <= 2; off <<= 1) {
            mx_lo = fmaxf(mx_lo, __shfl_xor_sync(0xffffffffu, mx_lo, off));
            mx_hi = fmaxf(mx_hi, __shfl_xor_sync(0xffffffffu, mx_hi, off));
        }

        float newm_lo = fmaxf(m_lo, mx_lo);
        float newm_hi = fmaxf(m_hi, mx_hi);
        float alpha_lo = __expf(m_lo - newm_lo);
        float alpha_hi = __expf(m_hi - newm_hi);

        float sum_lo = 0.0f, sum_hi = 0.0f;
        #pragma unroll
        for (int nt = 0; nt < 8; nt++) {
            sc[nt][0] = __expf(sc[nt][0] - newm_lo);
            sc[nt][1] = __expf(sc[nt][1] - newm_lo);
            sc[nt][2] = __expf(sc[nt][2] - newm_hi);
            sc[nt][3] = __expf(sc[nt][3] - newm_hi);
            sum_lo += sc[nt][0] + sc[nt][1];
            sum_hi += sc[nt][2] + sc[nt][3];
        }
        #pragma unroll
        for (int off = 1; off <= 2; off <<= 1) {
            sum_lo += __shfl_xor_sync(0xffffffffu, sum_lo, off);
            sum_hi += __shfl_xor_sync(0xffffffffu, sum_hi, off);
        }

        l_lo = l_lo * alpha_lo + sum_lo;
        l_hi = l_hi * alpha_hi + sum_hi;
        m_lo = newm_lo;
        m_hi = newm_hi;

        #pragma unroll
        for (int nt = 0; nt < 8; nt++) {
            o[nt][0] *= alpha_lo; o[nt][1] *= alpha_lo;
            o[nt][2] *= alpha_hi; o[nt][3] *= alpha_hi;
        }

        // P: repack S C-frags -> PV A-frags (no smem round trip)
        unsigned pa[4][4];
        #pragma unroll
        for (int s = 0; s < 4; s++) {
            pa[s][0] = pack2(sc[2 * s][0], sc[2 * s][1]);
            pa[s][1] = pack2(sc[2 * s][2], sc[2 * s][3]);
            pa[s][2] = pack2(sc[2 * s + 1][0], sc[2 * s + 1][1]);
            pa[s][3] = pack2(sc[2 * s + 1][2], sc[2 * s + 1][3]);
        }

        // O += P @ V
        #pragma unroll
        for (int s = 0; s < 4; s++) {
            unsigned vb[8][2];
            #pragma unroll
            for (int p = 0; p < 4; p++) {
                int trow = s * 16 + (sel & 1) * 8 + lrow;
                unsigned r0, r1, r2, r3;
                ldsm_x4_t(r0, r1, r2, r3,
                          vs + trow * FSTB + (p * 2 + (sel >> 1)) * 16);
                vb[p * 2][0] = r0; vb[p * 2][1] = r1;
                vb[p * 2 + 1][0] = r2; vb[p * 2 + 1][1] = r3;
            }
            #pragma unroll
            for (int nt = 0; nt < 8; nt++)
                mma_f16(o[nt], pa[s][0], pa[s][1], pa[s][2], pa[s][3],
                        vb[nt][0], vb[nt][1]);
        }
    }

    // epilogue: normalize, write fp16 [B,T,D]
    float inv_lo = 1.0f / l_lo;
    float inv_hi = 1.0f / l_hi;
    __half* out_lo = out + (size_t)(b * TT + q0 + rbase + gid    ) * DD + h * HD;
    __half* out_hi = out + (size_t)(b * TT + q0 + rbase + gid + 8) * DD + h * HD;
    #pragma unroll
    for (int nt = 0; nt < 8; nt++) {
        int cc = nt * 8 + tig * 2;
        *(unsigned*)(out_lo + cc) = pack2(o[nt][0] * inv_lo, o[nt][1] * inv_lo);
        *(unsigned*)(out_hi + cc) = pack2(o[nt][2] * inv_hi, o[nt][3] * inv_hi);
    }
}

// ---------------------------------------------------------------------------
extern "C" void kernel_launch(void* const* d_in, const int* in_sizes, int n_in,
                              void* d_out, int out_size)
{
    const float* x     = (const float*)d_in[0]; // [B,T,D]
    const float* w_qkv = (const float*)d_in[1]; // [D,3D]
    const float* w_out = (const float*)d_in[2]; // [D,D]
    float* out = (float*)d_out;                 // [B,T,D]

    float *qkv;
    __half *atth, *xh, *wqh, *woh;
    cudaGetSymbolAddress((void**)&qkv, g_qkv);
    cudaGetSymbolAddress((void**)&atth, g_atth);
    cudaGetSymbolAddress((void**)&xh, g_xh);
    cudaGetSymbolAddress((void**)&wqh, g_wqh);
    cudaGetSymbolAddress((void**)&woh, g_woh);

    const int M = BB * TT; // 4096
    const int nx = M * DD, nwq = DD * 3 * DD, nwo = DD * DD;

    // 0. convert inputs to fp16
    f2h_k<<<(nx  / 8 + 255) / 256, 256>>>(x, xh, nx);
    f2h_k<<<(nwq / 8 + 255) / 256, 256>>>(w_qkv, wqh, nwq);
    f2h_k<<<(nwo / 8 + 255) / 256, 256>>>(w_out, woh, nwo);

    // 1. qkv = x @ w_qkv  (fp16 tensor cores)
    gemm_f16<<<dim3((3 * DD) / 128, M / 128), 256, GH_SMEM>>>(xh, wqh, qkv,
                                                              M, 3 * DD, DD);
    // 2. RoPE on q,k in place (fp32)
    rope_k<<<(M * 2 * HH * 32) / 256, 256>>>(qkv);
    // 3. causal flash attention (fp16 tensor cores) -> atth (fp16)
    flash_f16<<<dim3(TT / 64, BB * HH), 128, FLASH_H_SMEM>>>(qkv, atth);
    // 4. out = att @ w_out  (fp16 tensor cores)
    gemm_f16<<<dim3(DD / 128, M / 128), 256, GH_SMEM>>>(atth, woh, out,
                                                        M, DD, DD);
}

// round 14
// speedup vs baseline: 6.3841x; 1.0947x over previous
#include <cuda_runtime.h>
#include <cuda_fp16.h>
#include <math.h>

// Problem constants
#define BB 2
#define TT 2048
#define DD 1024
#define HH 16
#define HD 64

// Scratch (device globals; no runtime allocation allowed)
__device__ __half g_qkvh[(size_t)BB * TT * 3 * DD]; // [B*T, 3D] q|k|v fp16
__device__ __half g_atth[(size_t)BB * TT * DD];     // attention out, fp16
__device__ __half g_xh[(size_t)BB * TT * DD];       // x in fp16
__device__ __half g_wqh[(size_t)DD * 3 * DD];       // w_qkv fp16 [K][N]
__device__ __half g_woh[(size_t)DD * DD];           // w_out fp16 [K][N]

__device__ __forceinline__ unsigned pack2(float a, float b) {
    __half2 h = __floats2half2_rn(a, b);
    return *(unsigned*)&h;
}

__device__ __forceinline__ void mma_f16(float c[4], unsigned a0, unsigned a1,
                                        unsigned a2, unsigned a3,
                                        unsigned b0, unsigned b1) {
    asm volatile(
        "mma.sync.aligned.m16n8k16.row.col.f32.f16.f16.f32 "
        "{%0,%1,%2,%3}, {%4,%5,%6,%7}, {%8,%9}, {%0,%1,%2,%3};\n"
        : "+f"(c[0]), "+f"(c[1]), "+f"(c[2]), "+f"(c[3])
        : "r"(a0), "r"(a1), "r"(a2), "r"(a3), "r"(b0), "r"(b1));
}

__device__ __forceinline__ void ldsm_x4(unsigned& r0, unsigned& r1,
                                        unsigned& r2, unsigned& r3, unsigned a) {
    asm volatile("ldmatrix.sync.aligned.m8n8.x4.shared.b16 {%0,%1,%2,%3}, [%4];"
                 : "=r"(r0), "=r"(r1), "=r"(r2), "=r"(r3) : "r"(a));
}
__device__ __forceinline__ void ldsm_x4_t(unsigned& r0, unsigned& r1,
                                          unsigned& r2, unsigned& r3, unsigned a) {
    asm volatile("ldmatrix.sync.aligned.m8n8.x4.trans.shared.b16 {%0,%1,%2,%3}, [%4];"
                 : "=r"(r0), "=r"(r1), "=r"(r2), "=r"(r3) : "r"(a));
}

__device__ __forceinline__ void cp_async16_s(unsigned saddr, const void* g) {
    asm volatile("cp.async.cg.shared.global [%0], [%1], 16;\n"
                 :: "r"(saddr), "l"(g));
}
#define CP_COMMIT() asm volatile("cp.async.commit_group;\n" ::: "memory")
#define CP_WAIT1()  asm volatile("cp.async.wait_group 1;\n" ::: "memory")
#define CP_WAIT0()  asm volatile("cp.async.wait_group 0;\n" ::: "memory")

// ---------------------------------------------------------------------------
// fp32 -> fp16 elementwise (8 per thread)
// ---------------------------------------------------------------------------
__global__ __launch_bounds__(256) void f2h_k(const float* __restrict__ src,
                                             __half* __restrict__ dst, int n)
{
    int i = (blockIdx.x * blockDim.x + threadIdx.x) * 8;
    if (i >= n) return;
    float4 v0 = *(const float4*)(src + i);
    float4 v1 = *(const float4*)(src + i + 4);
    uint4 u = make_uint4(pack2(v0.x, v0.y), pack2(v0.z, v0.w),
                         pack2(v1.x, v1.y), pack2(v1.z, v1.w));
    *(uint4*)(dst + i) = u;
}

// ---------------------------------------------------------------------------
// fp16 tensor-core GEMM: C[M,N] = A[M,K] @ B[K,N].
// OutT = float or __half. Block 128x128x32, 256 threads, warp tile 64x32.
// ---------------------------------------------------------------------------
#define BKH 32
#define A_ST 80
#define B_ST 272
#define A_STAGEB (128 * A_ST)
#define B_STAGEB (BKH * B_ST)
#define STAGEB (A_STAGEB + B_STAGEB)
#define GH_SMEM (2 * STAGEB)

template <typename OutT>
__global__ __launch_bounds__(256, 2) void gemm_f16(const __half* __restrict__ A,
                                                   const __half* __restrict__ B,
                                                   OutT* __restrict__ C,
                                                   int M, int N, int K)
{
    extern __shared__ unsigned char hsm[];
    const unsigned sbase = (unsigned)__cvta_generic_to_shared(hsm);

    const int tid  = threadIdx.x;
    const int warp = tid >> 5;
    const int lane = tid & 31;
    const int wm   = warp >> 2;
    const int wn   = warp & 3;
    const int gid  = lane >> 2;
    const int tig  = lane & 3;
    const int sel  = lane >> 3;
    const int lrow = lane & 7;

    const int cRow = blockIdx.y * 128;
    const int cCol = blockIdx.x * 128;

    float c[4][4][4];
    #pragma unroll
    for (int mt = 0; mt < 4; mt++)
        #pragma unroll
        for (int nt = 0; nt < 4; nt++)
            #pragma unroll
            for (int r = 0; r < 4; r++) c[mt][nt][r] = 0.0f;

    const int ntiles = K / BKH;

    auto load_stage = [&](int t) {
        unsigned bufA = sbase + (t & 1) * STAGEB;
        unsigned bufB = bufA + A_STAGEB;
        int k0 = t * BKH;
        #pragma unroll
        for (int j = 0; j < 2; j++) {
            int i = tid + j * 256;
            int r = i >> 2, cc = i & 3;
            cp_async16_s(bufA + r * A_ST + cc * 16,
                         A + (size_t)(cRow + r) * K + k0 + cc * 8);
            int k = i >> 4, bc = i & 15;
            cp_async16_s(bufB + k * B_ST + bc * 16,
                         B + (size_t)(k0 + k) * N + cCol + bc * 8);
        }
        CP_COMMIT();
    };

    load_stage(0);

    for (int t = 0; t < ntiles; t++) {
        if (t + 1 < ntiles) {
            load_stage(t + 1);
            CP_WAIT1();
        } else {
            CP_WAIT0();
        }
        __syncthreads();

        unsigned bufA = sbase + (t & 1) * STAGEB;
        unsigned bufB = bufA + A_STAGEB;

        #pragma unroll
        for (int s = 0; s < 2; s++) {
            unsigned af[4][4];
            #pragma unroll
            for (int mt = 0; mt < 4; mt++) {
                int row = wm * 64 + mt * 16 + (sel & 1) * 8 + lrow;
                ldsm_x4(af[mt][0], af[mt][1], af[mt][2], af[mt][3],
                        bufA + row * A_ST + s * 32 + (sel >> 1) * 16);
            }
            unsigned bf[4][2];
            #pragma unroll
            for (int p = 0; p < 2; p++) {
                int krow = s * 16 + (sel & 1) * 8 + lrow;
                int ncol = wn * 32 + (p * 2 + (sel >> 1)) * 8;
                unsigned r0, r1, r2, r3;
                ldsm_x4_t(r0, r1, r2, r3, bufB + krow * B_ST + ncol * 2);
                bf[p * 2][0] = r0; bf[p * 2][1] = r1;
                bf[p * 2 + 1][0] = r2; bf[p * 2 + 1][1] = r3;
            }
            #pragma unroll
            for (int mt = 0; mt < 4; mt++)
                #pragma unroll
                for (int nt = 0; nt < 4; nt++)
                    mma_f16(c[mt][nt], af[mt][0], af[mt][1], af[mt][2], af[mt][3],
                            bf[nt][0], bf[nt][1]);
        }
        __syncthreads();
    }

    #pragma unroll
    for (int mt = 0; mt < 4; mt++) {
        #pragma unroll
        for (int nt = 0; nt < 4; nt++) {
            int row = cRow + wm * 64 + mt * 16 + gid;
            int col = cCol + wn * 32 + nt * 8 + tig * 2;
            if (sizeof(OutT) == 4) {
                *(float2*)((float*)C + (size_t)row * N + col) =
                    make_float2(c[mt][nt][0], c[mt][nt][1]);
                *(float2*)((float*)C + (size_t)(row + 8) * N + col) =
                    make_float2(c[mt][nt][2], c[mt][nt][3]);
            } else {
                *(unsigned*)((__half*)C + (size_t)row * N + col) =
                    pack2(c[mt][nt][0], c[mt][nt][1]);
                *(unsigned*)((__half*)C + (size_t)(row + 8) * N + col) =
                    pack2(c[mt][nt][2], c[mt][nt][3]);
            }
        }
    }
}

// ---------------------------------------------------------------------------
// RoPE in place on fp16 q,k halves of qkv (fp32 internal math).
// ---------------------------------------------------------------------------
__global__ __launch_bounds__(256) void rope_h(__half* __restrict__ qkv)
{
    int idx = blockIdx.x * blockDim.x + threadIdx.x;
    int j     = idx & 31;
    int h     = (idx >> 5) & 15;
    int which = (idx >> 9) & 1;
    int bt    = idx >> 10;
    if (bt >= BB * TT) return;

    int t = bt & (TT - 1);
    float inv = powf(10000.0f, -(float)j * (1.0f / 32.0f));
    float ang = (float)t * inv;
    float s, c;
    sincosf(ang, &s, &c);

    __half* base = qkv + (size_t)bt * (3 * DD) + which * DD + h * HD;
    float x1 = __half2float(base[j]);
    float x2 = __half2float(base[j + 32]);
    base[j]      = __float2half(x1 * c - x2 * s);
    base[j + 32] = __float2half(x2 * c + x1 * s);
}

// ---------------------------------------------------------------------------
// Causal flash attention, fp16 mma m16n8k16.
// Block = 128 q-rows of one (b,h), 256 threads / 8 warps; warp owns 16 rows.
// K/V tiles are 64 rows. Causal warp-skip on fully-masked warp tiles.
// ---------------------------------------------------------------------------
#define FST 72
#define FSTB 144
#define FLASH_H_SMEM ((128 + 64 + 64) * FSTB)   // 36864

__global__ __launch_bounds__(256) void flash_f16(const __half* __restrict__ qkv,
                                                 __half* __restrict__ out)
{
    extern __shared__ __half fsm[];
    __half* Qs = fsm;                 // 128 x FST
    __half* Ks = fsm + 128 * FST;     // 64 x FST
    __half* Vs = fsm + 192 * FST;     // 64 x FST
    const unsigned qs = (unsigned)__cvta_generic_to_shared(Qs);
    const unsigned ks = (unsigned)__cvta_generic_to_shared(Ks);
    const unsigned vs = (unsigned)__cvta_generic_to_shared(Vs);

    const int qt = blockIdx.x;
    const int bh = blockIdx.y;
    const int b  = bh >> 4;
    const int h  = bh & 15;
    const int tid  = threadIdx.x;
    const int warp = tid >> 5;
    const int lane = tid & 31;
    const int gid  = lane >> 2;
    const int tig  = lane & 3;
    const int sel  = lane >> 3;
    const int lrow = lane & 7;
    const int rbase = warp * 16;

    const int q0 = qt * 128;
    const __half* qg = qkv + ((size_t)(b * TT + q0)) * (3 * DD) + h * HD;

    // Q -> smem (scaled by 1/8)
    const __half2 hscale = __float2half2_rn(0.125f);
    for (int i = tid; i < 1024; i += 256) {
        int r = i >> 3, cc = i & 7;
        uint4 u = *(const uint4*)(qg + (size_t)r * (3 * DD) + cc * 8);
        __half2* hp = (__half2*)&u;
        hp[0] = __hmul2(hp[0], hscale);
        hp[1] = __hmul2(hp[1], hscale);
        hp[2] = __hmul2(hp[2], hscale);
        hp[3] = __hmul2(hp[3], hscale);
        *(uint4*)((char*)Qs + r * FSTB + cc * 16) = u;
    }
    __syncthreads();

    // Q fragments -> registers
    unsigned qf[4][4];
    #pragma unroll
    for (int s = 0; s < 4; s++) {
        int row = rbase + (sel & 1) * 8 + lrow;
        ldsm_x4(qf[s][0], qf[s][1], qf[s][2], qf[s][3],
                qs + row * FSTB + s * 32 + (sel >> 1) * 16);
    }

    float o[8][4];
    #pragma unroll
    for (int nt = 0; nt < 8; nt++)
        #pragma unroll
        for (int r = 0; r < 4; r++) o[nt][r] = 0.0f;
    float m_lo = -INFINITY, m_hi = -INFINITY;
    float l_lo = 0.0f, l_hi = 0.0f;

    const int row_lo = q0 + rbase + gid;
    const int row_hi = row_lo + 8;
    const int wrow_max = q0 + rbase + 15;

    const int nkt = 2 * qt + 2;   // k tiles of 64 covering [0, q0+128)

    for (int kt = 0; kt < nkt; kt++) {
        const int k0 = kt * 64;
        const __half* kg = qkv + ((size_t)(b * TT + k0)) * (3 * DD) + DD + h * HD;
        const __half* vg = qkv + ((size_t)(b * TT + k0)) * (3 * DD) + 2 * DD + h * HD;

        __syncthreads();
        for (int i = tid; i < 512; i += 256) {
            int r = i >> 3, cc = i & 7;
            *(uint4*)((char*)Ks + r * FSTB + cc * 16) =
                *(const uint4*)(kg + (size_t)r * (3 * DD) + cc * 8);
            *(uint4*)((char*)Vs + r * FSTB + cc * 16) =
                *(const uint4*)(vg + (size_t)r * (3 * DD) + cc * 8);
        }
        __syncthreads();

        if (k0 > wrow_max) continue;   // whole warp tile above diagonal

        // S = Q K^T
        float sc[8][4];
        #pragma unroll
        for (int nt = 0; nt < 8; nt++)
            #pragma unroll
            for (int r = 0; r < 4; r++) sc[nt][r] = 0.0f;

        #pragma unroll
        for (int s = 0; s < 4; s++) {
            unsigned kb[8][2];
            #pragma unroll
            for (int p = 0; p < 4; p++) {
                int trow = (p * 2 + (sel >> 1)) * 8 + lrow;
                unsigned r0, r1, r2, r3;
                ldsm_x4(r0, r1, r2, r3,
                        ks + trow * FSTB + s * 32 + (sel & 1) * 16);
                kb[p * 2][0] = r0; kb[p * 2][1] = r1;
                kb[p * 2 + 1][0] = r2; kb[p * 2 + 1][1] = r3;
            }
            #pragma unroll
            for (int nt = 0; nt < 8; nt++)
                mma_f16(sc[nt], qf[s][0], qf[s][1], qf[s][2], qf[s][3],
                        kb[nt][0], kb[nt][1]);
        }

        if (k0 + 63 > row_lo) {   // diagonal region for this warp
            #pragma unroll
            for (int nt = 0; nt < 8; nt++) {
                int c0 = k0 + nt * 8 + tig * 2;
                if (c0     > row_lo) sc[nt][0] = -INFINITY;
                if (c0 + 1 > row_lo) sc[nt][1] = -INFINITY;
                if (c0     > row_hi) sc[nt][2] = -INFINITY;
                if (c0 + 1 > row_hi) sc[nt][3] = -INFINITY;
            }
        }

        float mx_lo = -INFINITY, mx_hi = -INFINITY;
        #pragma unroll
        for (int nt = 0; nt < 8; nt++) {
            mx_lo = fmaxf(mx_lo, fmaxf(sc[nt][0], sc[nt][1]));
            mx_hi = fmaxf(mx_hi, fmaxf(sc[nt][2], sc[nt][3]));
        }
        #pragma unroll
        for (int off = 1; off <= 2; off <<= 1) {
            mx_lo = fmaxf(mx_lo, __shfl_xor_sync(0xffffffffu, mx_lo, off));
            mx_hi = fmaxf(mx_hi, __shfl_xor_sync(0xffffffffu, mx_hi, off));
        }

        float newm_lo = fmaxf(m_lo, mx_lo);
        float newm_hi = fmaxf(m_hi, mx_hi);
        float alpha_lo = __expf(m_lo - newm_lo);
        float alpha_hi = __expf(m_hi - newm_hi);

        float sum_lo = 0.0f, sum_hi = 0.0f;
        #pragma unroll
        for (int nt = 0; nt < 8; nt++) {
            sc[nt][0] = __expf(sc[nt][0] - newm_lo);
            sc[nt][1] = __expf(sc[nt][1] - newm_lo);
            sc[nt][2] = __expf(sc[nt][2] - newm_hi);
            sc[nt][3] = __expf(sc[nt][3] - newm_hi);
            sum_lo += sc[nt][0] + sc[nt][1];
            sum_hi += sc[nt][2] + sc[nt][3];
        }
        #pragma unroll
        for (int off = 1; off <= 2; off <<= 1) {
            sum_lo += __shfl_xor_sync(0xffffffffu, sum_lo, off);
            sum_hi += __shfl_xor_sync(0xffffffffu, sum_hi, off);
        }

        l_lo = l_lo * alpha_lo + sum_lo;
        l_hi = l_hi * alpha_hi + sum_hi;
        m_lo = newm_lo;
        m_hi = newm_hi;

        #pragma unroll
        for (int nt = 0; nt < 8; nt++) {
            o[nt][0] *= alpha_lo; o[nt][1] *= alpha_lo;
            o[nt][2] *= alpha_hi; o[nt][3] *= alpha_hi;
        }

        // P: repack S C-frags -> PV A-frags
        unsigned pa[4][4];
        #pragma unroll
        for (int s = 0; s < 4; s++) {
            pa[s][0] = pack2(sc[2 * s][0], sc[2 * s][1]);
            pa[s][1] = pack2(sc[2 * s][2], sc[2 * s][3]);
            pa[s][2] = pack2(sc[2 * s + 1][0], sc[2 * s + 1][1]);
            pa[s][3] = pack2(sc[2 * s + 1][2], sc[2 * s + 1][3]);
        }

        // O += P @ V
        #pragma unroll
        for (int s = 0; s < 4; s++) {
            unsigned vb[8][2];
            #pragma unroll
            for (int p = 0; p < 4; p++) {
                int trow = s * 16 + (sel & 1) * 8 + lrow;
                unsigned r0, r1, r2, r3;
                ldsm_x4_t(r0, r1, r2, r3,
                          vs + trow * FSTB + (p * 2 + (sel >> 1)) * 16);
                vb[p * 2][0] = r0; vb[p * 2][1] = r1;
                vb[p * 2 + 1][0] = r2; vb[p * 2 + 1][1] = r3;
            }
            #pragma unroll
            for (int nt = 0; nt < 8; nt++)
                mma_f16(o[nt], pa[s][0], pa[s][1], pa[s][2], pa[s][3],
                        vb[nt][0], vb[nt][1]);
        }
    }

    // epilogue: normalize, write fp16 [B,T,D]
    float inv_lo = 1.0f / l_lo;
    float inv_hi = 1.0f / l_hi;
    __half* out_lo = out + (size_t)(b * TT + q0 + rbase + gid    ) * DD + h * HD;
    __half* out_hi = out + (size_t)(b * TT + q0 + rbase + gid + 8) * DD + h * HD;
    #pragma unroll
    for (int nt = 0; nt < 8; nt++) {
        int cc = nt * 8 + tig * 2;
        *(unsigned*)(out_lo + cc) = pack2(o[nt][0] * inv_lo, o[nt][1] * inv_lo);
        *(unsigned*)(out_hi + cc) = pack2(o[nt][2] * inv_hi, o[nt][3] * inv_hi);
    }
}

// ---------------------------------------------------------------------------
extern "C" void kernel_launch(void* const* d_in, const int* in_sizes, int n_in,
                              void* d_out, int out_size)
{
    const float* x     = (const float*)d_in[0]; // [B,T,D]
    const float* w_qkv = (const float*)d_in[1]; // [D,3D]
    const float* w_out = (const float*)d_in[2]; // [D,D]
    float* out = (float*)d_out;                 // [B,T,D]

    __half *qkvh, *atth, *xh, *wqh, *woh;
    cudaGetSymbolAddress((void**)&qkvh, g_qkvh);
    cudaGetSymbolAddress((void**)&atth, g_atth);
    cudaGetSymbolAddress((void**)&xh, g_xh);
    cudaGetSymbolAddress((void**)&wqh, g_wqh);
    cudaGetSymbolAddress((void**)&woh, g_woh);

    const int M = BB * TT; // 4096
    const int nx = M * DD, nwq = DD * 3 * DD, nwo = DD * DD;

    // 0. convert inputs to fp16
    f2h_k<<<(nx  / 8 + 255) / 256, 256>>>(x, xh, nx);
    f2h_k<<<(nwq / 8 + 255) / 256, 256>>>(w_qkv, wqh, nwq);
    f2h_k<<<(nwo / 8 + 255) / 256, 256>>>(w_out, woh, nwo);

    // 1. qkv = x @ w_qkv  (fp16 tensor cores, fp16 output)
    gemm_f16<__half><<<dim3((3 * DD) / 128, M / 128), 256, GH_SMEM>>>(
        xh, wqh, qkvh, M, 3 * DD, DD);
    // 2. RoPE on q,k in place (fp16)
    rope_h<<<(M * 2 * HH * 32) / 256, 256>>>(qkvh);
    // 3. causal flash attention (fp16) -> atth
    flash_f16<<<dim3(TT / 128, BB * HH), 256, FLASH_H_SMEM>>>(qkvh, atth);
    // 4. out = att @ w_out  (fp16 tensor cores, fp32 output)
    gemm_f16<float><<<dim3(DD / 128, M / 128), 256, GH_SMEM>>>(
        atth, woh, out, M, DD, DD);
}

// round 15
// speedup vs baseline: 6.8287x; 1.0696x over previous
#include <cuda_runtime.h>
#include <cuda_fp16.h>
#include <math.h>

// Problem constants
#define BB 2
#define TT 2048
#define DD 1024
#define HH 16
#define HD 64

// Scratch (device globals; no runtime allocation allowed)
__device__ __half g_qkvh[(size_t)BB * TT * 3 * DD]; // [B*T, 3D] q|k|v fp16 (rope applied)
__device__ __half g_atth[(size_t)BB * TT * DD];     // attention out, fp16
__device__ __half g_xh[(size_t)BB * TT * DD];       // x in fp16
__device__ __half g_wqh[(size_t)DD * 3 * DD];       // w_qkv fp16 [K][N]
__device__ __half g_woh[(size_t)DD * DD];           // w_out fp16 [K][N]

__device__ __forceinline__ unsigned pack2(float a, float b) {
    __half2 h = __floats2half2_rn(a, b);
    return *(unsigned*)&h;
}

__device__ __forceinline__ void mma_f16(float c[4], unsigned a0, unsigned a1,
                                        unsigned a2, unsigned a3,
                                        unsigned b0, unsigned b1) {
    asm volatile(
        "mma.sync.aligned.m16n8k16.row.col.f32.f16.f16.f32 "
        "{%0,%1,%2,%3}, {%4,%5,%6,%7}, {%8,%9}, {%0,%1,%2,%3};\n"
        : "+f"(c[0]), "+f"(c[1]), "+f"(c[2]), "+f"(c[3])
        : "r"(a0), "r"(a1), "r"(a2), "r"(a3), "r"(b0), "r"(b1));
}

__device__ __forceinline__ void ldsm_x4(unsigned& r0, unsigned& r1,
                                        unsigned& r2, unsigned& r3, unsigned a) {
    asm volatile("ldmatrix.sync.aligned.m8n8.x4.shared.b16 {%0,%1,%2,%3}, [%4];"
                 : "=r"(r0), "=r"(r1), "=r"(r2), "=r"(r3) : "r"(a));
}
__device__ __forceinline__ void ldsm_x4_t(unsigned& r0, unsigned& r1,
                                          unsigned& r2, unsigned& r3, unsigned a) {
    asm volatile("ldmatrix.sync.aligned.m8n8.x4.trans.shared.b16 {%0,%1,%2,%3}, [%4];"
                 : "=r"(r0), "=r"(r1), "=r"(r2), "=r"(r3) : "r"(a));
}

__device__ __forceinline__ void cp_async16_s(unsigned saddr, const void* g) {
    asm volatile("cp.async.cg.shared.global [%0], [%1], 16;\n"
                 :: "r"(saddr), "l"(g));
}
#define CP_COMMIT() asm volatile("cp.async.commit_group;\n" ::: "memory")
#define CP_WAIT1()  asm volatile("cp.async.wait_group 1;\n" ::: "memory")
#define CP_WAIT0()  asm volatile("cp.async.wait_group 0;\n" ::: "memory")

// ---------------------------------------------------------------------------
// fp32 -> fp16 elementwise (8 per thread)
// ---------------------------------------------------------------------------
__global__ __launch_bounds__(256) void f2h_k(const float* __restrict__ src,
                                             __half* __restrict__ dst, int n)
{
    int i = (blockIdx.x * blockDim.x + threadIdx.x) * 8;
    if (i >= n) return;
    float4 v0 = *(const float4*)(src + i);
    float4 v1 = *(const float4*)(src + i + 4);
    uint4 u = make_uint4(pack2(v0.x, v0.y), pack2(v0.z, v0.w),
                         pack2(v1.x, v1.y), pack2(v1.z, v1.w));
    *(uint4*)(dst + i) = u;
}

// ---------------------------------------------------------------------------
// fp16 tensor-core GEMM: C[M,N] = A[M,K] @ B[K,N].
// Warp's N columns are the 4 groups {wn*8 + nt*32} so that accumulator pairs
// (nt, nt+1) hold head-cols (j, j+32) => RoPE can be applied in the epilogue
// (ROPE=true, cols < 2*DD). OutT = float or __half.
// ---------------------------------------------------------------------------
#define BKH 32
#define A_ST 80
#define B_ST 272
#define A_STAGEB (128 * A_ST)
#define B_STAGEB (BKH * B_ST)
#define STAGEB (A_STAGEB + B_STAGEB)
#define GH_SMEM (2 * STAGEB)

template <typename OutT, bool ROPE>
__global__ __launch_bounds__(256, 2) void gemm_f16(const __half* __restrict__ A,
                                                   const __half* __restrict__ B,
                                                   OutT* __restrict__ C,
                                                   int M, int N, int K)
{
    extern __shared__ unsigned char hsm[];
    const unsigned sbase = (unsigned)__cvta_generic_to_shared(hsm);

    const int tid  = threadIdx.x;
    const int warp = tid >> 5;
    const int lane = tid & 31;
    const int wm   = warp >> 2;
    const int wn   = warp & 3;
    const int gid  = lane >> 2;
    const int tig  = lane & 3;
    const int sel  = lane >> 3;
    const int lrow = lane & 7;

    const int cRow = blockIdx.y * 128;
    const int cCol = blockIdx.x * 128;

    float c[4][4][4];
    #pragma unroll
    for (int mt = 0; mt < 4; mt++)
        #pragma unroll
        for (int nt = 0; nt < 4; nt++)
            #pragma unroll
            for (int r = 0; r < 4; r++) c[mt][nt][r] = 0.0f;

    const int ntiles = K / BKH;

    auto load_stage = [&](int t) {
        unsigned bufA = sbase + (t & 1) * STAGEB;
        unsigned bufB = bufA + A_STAGEB;
        int k0 = t * BKH;
        #pragma unroll
        for (int j = 0; j < 2; j++) {
            int i = tid + j * 256;
            int r = i >> 2, cc = i & 3;
            cp_async16_s(bufA + r * A_ST + cc * 16,
                         A + (size_t)(cRow + r) * K + k0 + cc * 8);
            int k = i >> 4, bc = i & 15;
            cp_async16_s(bufB + k * B_ST + bc * 16,
                         B + (size_t)(k0 + k) * N + cCol + bc * 8);
        }
        CP_COMMIT();
    };

    load_stage(0);

    for (int t = 0; t < ntiles; t++) {
        if (t + 1 < ntiles) {
            load_stage(t + 1);
            CP_WAIT1();
        } else {
            CP_WAIT0();
        }
        __syncthreads();

        unsigned bufA = sbase + (t & 1) * STAGEB;
        unsigned bufB = bufA + A_STAGEB;

        #pragma unroll
        for (int s = 0; s < 2; s++) {
            unsigned af[4][4];
            #pragma unroll
            for (int mt = 0; mt < 4; mt++) {
                int row = wm * 64 + mt * 16 + (sel & 1) * 8 + lrow;
                ldsm_x4(af[mt][0], af[mt][1], af[mt][2], af[mt][3],
                        bufA + row * A_ST + s * 32 + (sel >> 1) * 16);
            }
            unsigned bf[4][2];
            #pragma unroll
            for (int p = 0; p < 2; p++) {
                int krow = s * 16 + (sel & 1) * 8 + lrow;
                // matrix m col group: wn*8 + (sel>>1)*32 + p*64
                int ncol = wn * 8 + (sel >> 1) * 32 + p * 64;
                unsigned r0, r1, r2, r3;
                ldsm_x4_t(r0, r1, r2, r3, bufB + krow * B_ST + ncol * 2);
                bf[p * 2][0] = r0; bf[p * 2][1] = r1;      // col wn*8 + p*64
                bf[p * 2 + 1][0] = r2; bf[p * 2 + 1][1] = r3; // col wn*8+32 + p*64
            }
            #pragma unroll
            for (int mt = 0; mt < 4; mt++)
                #pragma unroll
                for (int nt = 0; nt < 4; nt++)
                    mma_f16(c[mt][nt], af[mt][0], af[mt][1], af[mt][2], af[mt][3],
                            bf[nt][0], bf[nt][1]);
        }
        __syncthreads();
    }

    // epilogue (optionally fused RoPE for q/k regions)
    const bool is_qk = ROPE && (cCol < 2 * DD);
    float inv0 = 0.0f, inv1 = 0.0f;
    if (is_qk) {
        float j0 = (float)(wn * 8 + tig * 2);
        inv0 = powf(10000.0f, -j0 * (1.0f / 32.0f));
        inv1 = powf(10000.0f, -(j0 + 1.0f) * (1.0f / 32.0f));
    }

    #pragma unroll
    for (int mt = 0; mt < 4; mt++) {
        int row = cRow + wm * 64 + mt * 16 + gid;
        if (is_qk) {
            int t0 = row & (TT - 1);
            int t1 = (row + 8) & (TT - 1);
            float s00, c00, s01, c01, s10, c10, s11, c11;
            sincosf((float)t0 * inv0, &s00, &c00);
            sincosf((float)t0 * inv1, &s01, &c01);
            sincosf((float)t1 * inv0, &s10, &c10);
            sincosf((float)t1 * inv1, &s11, &c11);
            #pragma unroll
            for (int p = 0; p < 4; p += 2) {
                float x1, x2;
                x1 = c[mt][p][0]; x2 = c[mt][p + 1][0];
                c[mt][p][0] = x1 * c00 - x2 * s00;
                c[mt][p + 1][0] = x2 * c00 + x1 * s00;
                x1 = c[mt][p][1]; x2 = c[mt][p + 1][1];
                c[mt][p][1] = x1 * c01 - x2 * s01;
                c[mt][p + 1][1] = x2 * c01 + x1 * s01;
                x1 = c[mt][p][2]; x2 = c[mt][p + 1][2];
                c[mt][p][2] = x1 * c10 - x2 * s10;
                c[mt][p + 1][2] = x2 * c10 + x1 * s10;
                x1 = c[mt][p][3]; x2 = c[mt][p + 1][3];
                c[mt][p][3] = x1 * c11 - x2 * s11;
                c[mt][p + 1][3] = x2 * c11 + x1 * s11;
            }
        }
        #pragma unroll
        for (int nt = 0; nt < 4; nt++) {
            int col = cCol + wn * 8 + nt * 32 + tig * 2;
            if (sizeof(OutT) == 4) {
                *(float2*)((float*)C + (size_t)row * N + col) =
                    make_float2(c[mt][nt][0], c[mt][nt][1]);
                *(float2*)((float*)C + (size_t)(row + 8) * N + col) =
                    make_float2(c[mt][nt][2], c[mt][nt][3]);
            } else {
                *(unsigned*)((__half*)C + (size_t)row * N + col) =
                    pack2(c[mt][nt][0], c[mt][nt][1]);
                *(unsigned*)((__half*)C + (size_t)(row + 8) * N + col) =
                    pack2(c[mt][nt][2], c[mt][nt][3]);
            }
        }
    }
}

// ---------------------------------------------------------------------------
// Causal flash attention, fp16 mma m16n8k16.
// Block = 128 q-rows of one (b,h), 256 threads / 8 warps; warp owns 16 rows.
// K/V 64-row tiles, cp.async double-buffered. Causal warp-skip.
// ---------------------------------------------------------------------------
#define FST 72
#define FSTB 144
#define KV_SLOT (64 * FSTB)                       // 9216 B per K or V tile
#define FLASH_H_SMEM (128 * FSTB + 4 * KV_SLOT)   // Q + 2*(K+V) = 55296

__global__ __launch_bounds__(256) void flash_f16(const __half* __restrict__ qkv,
                                                 __half* __restrict__ out)
{
    extern __shared__ __half fsm[];
    const unsigned qs  = (unsigned)__cvta_generic_to_shared(fsm);
    const unsigned kv0 = qs + 128 * FSTB;   // [K0 V0 K1 V1]

    const int qt = blockIdx.x;
    const int bh = blockIdx.y;
    const int b  = bh >> 4;
    const int h  = bh & 15;
    const int tid  = threadIdx.x;
    const int warp = tid >> 5;
    const int lane = tid & 31;
    const int gid  = lane >> 2;
    const int tig  = lane & 3;
    const int sel  = lane >> 3;
    const int lrow = lane & 7;
    const int rbase = warp * 16;

    const int q0 = qt * 128;
    const __half* qg = qkv + ((size_t)(b * TT + q0)) * (3 * DD) + h * HD;
    const __half* kgb = qkv + (size_t)b * TT * 3 * DD + DD + h * HD;
    const __half* vgb = qkv + (size_t)b * TT * 3 * DD + 2 * DD + h * HD;

    // Q -> smem (scaled by 1/8)
    const __half2 hscale = __float2half2_rn(0.125f);
    for (int i = tid; i < 1024; i += 256) {
        int r = i >> 3, cc = i & 7;
        uint4 u = *(const uint4*)(qg + (size_t)r * (3 * DD) + cc * 8);
        __half2* hp = (__half2*)&u;
        hp[0] = __hmul2(hp[0], hscale);
        hp[1] = __hmul2(hp[1], hscale);
        hp[2] = __hmul2(hp[2], hscale);
        hp[3] = __hmul2(hp[3], hscale);
        *(uint4*)((char*)fsm + r * FSTB + cc * 16) = u;
    }

    auto load_kv = [&](int kt) {
        unsigned base = kv0 + (kt & 1) * (2 * KV_SLOT);
        const __half* kg = kgb + (size_t)(kt * 64) * (3 * DD);
        const __half* vg = vgb + (size_t)(kt * 64) * (3 * DD);
        #pragma unroll
        for (int j = 0; j < 2; j++) {
            int i = tid + j * 256;
            int r = i >> 3, cc = i & 7;
            cp_async16_s(base + r * FSTB + cc * 16,
                         kg + (size_t)r * (3 * DD) + cc * 8);
            cp_async16_s(base + KV_SLOT + r * FSTB + cc * 16,
                         vg + (size_t)r * (3 * DD) + cc * 8);
        }
        CP_COMMIT();
    };

    const int nkt = 2 * qt + 2;
    load_kv(0);

    __syncthreads();   // Q visible

    // Q fragments -> registers
    unsigned qf[4][4];
    #pragma unroll
    for (int s = 0; s < 4; s++) {
        int row = rbase + (sel & 1) * 8 + lrow;
        ldsm_x4(qf[s][0], qf[s][1], qf[s][2], qf[s][3],
                qs + row * FSTB + s * 32 + (sel >> 1) * 16);
    }

    float o[8][4];
    #pragma unroll
    for (int nt = 0; nt < 8; nt++)
        #pragma unroll
        for (int r = 0; r < 4; r++) o[nt][r] = 0.0f;
    float m_lo = -INFINITY, m_hi = -INFINITY;
    float l_lo = 0.0f, l_hi = 0.0f;

    const int row_lo = q0 + rbase + gid;
    const int row_hi = row_lo + 8;
    const int wrow_max = q0 + rbase + 15;

    for (int kt = 0; kt < nkt; kt++) {
        if (kt + 1 < nkt) {
            load_kv(kt + 1);
            CP_WAIT1();
        } else {
            CP_WAIT0();
        }
        __syncthreads();

        const unsigned ks = kv0 + (kt & 1) * (2 * KV_SLOT);
        const unsigned vs = ks + KV_SLOT;
        const int k0 = kt * 64;

        if (k0 <= wrow_max) {
            // S = Q K^T
            float sc[8][4];
            #pragma unroll
            for (int nt = 0; nt < 8; nt++)
                #pragma unroll
                for (int r = 0; r < 4; r++) sc[nt][r] = 0.0f;

            #pragma unroll
            for (int s = 0; s < 4; s++) {
                unsigned kb[8][2];
                #pragma unroll
                for (int p = 0; p < 4; p++) {
                    int trow = (p * 2 + (sel >> 1)) * 8 + lrow;
                    unsigned r0, r1, r2, r3;
                    ldsm_x4(r0, r1, r2, r3,
                            ks + trow * FSTB + s * 32 + (sel & 1) * 16);
                    kb[p * 2][0] = r0; kb[p * 2][1] = r1;
                    kb[p * 2 + 1][0] = r2; kb[p * 2 + 1][1] = r3;
                }
                #pragma unroll
                for (int nt = 0; nt < 8; nt++)
                    mma_f16(sc[nt], qf[s][0], qf[s][1], qf[s][2], qf[s][3],
                            kb[nt][0], kb[nt][1]);
            }

            if (k0 + 63 > row_lo) {
                #pragma unroll
                for (int nt = 0; nt < 8; nt++) {
                    int c0 = k0 + nt * 8 + tig * 2;
                    if (c0     > row_lo) sc[nt][0] = -INFINITY;
                    if (c0 + 1 > row_lo) sc[nt][1] = -INFINITY;
                    if (c0     > row_hi) sc[nt][2] = -INFINITY;
                    if (c0 + 1 > row_hi) sc[nt][3] = -INFINITY;
                }
            }

            float mx_lo = -INFINITY, mx_hi = -INFINITY;
            #pragma unroll
            for (int nt = 0; nt < 8; nt++) {
                mx_lo = fmaxf(mx_lo, fmaxf(sc[nt][0], sc[nt][1]));
                mx_hi = fmaxf(mx_hi, fmaxf(sc[nt][2], sc[nt][3]));
            }
            #pragma unroll
            for (int off = 1; off <= 2; off <<= 1) {
                mx_lo = fmaxf(mx_lo, __shfl_xor_sync(0xffffffffu, mx_lo, off));
                mx_hi = fmaxf(mx_hi, __shfl_xor_sync(0xffffffffu, mx_hi, off));
            }

            float newm_lo = fmaxf(m_lo, mx_lo);
            float newm_hi = fmaxf(m_hi, mx_hi);
            float alpha_lo = __expf(m_lo - newm_lo);
            float alpha_hi = __expf(m_hi - newm_hi);

            float sum_lo = 0.0f, sum_hi = 0.0f;
            #pragma unroll
            for (int nt = 0; nt < 8; nt++) {
                sc[nt][0] = __expf(sc[nt][0] - newm_lo);
                sc[nt][1] = __expf(sc[nt][1] - newm_lo);
                sc[nt][2] = __expf(sc[nt][2] - newm_hi);
                sc[nt][3] = __expf(sc[nt][3] - newm_hi);
                sum_lo += sc[nt][0] + sc[nt][1];
                sum_hi += sc[nt][2] + sc[nt][3];
            }
            #pragma unroll
            for (int off = 1; off <= 2; off <<= 1) {
                sum_lo += __shfl_xor_sync(0xffffffffu, sum_lo, off);
                sum_hi += __shfl_xor_sync(0xffffffffu, sum_hi, off);
            }

            l_lo = l_lo * alpha_lo + sum_lo;
            l_hi = l_hi * alpha_hi + sum_hi;
            m_lo = newm_lo;
            m_hi = newm_hi;

            #pragma unroll
            for (int nt = 0; nt < 8; nt++) {
                o[nt][0] *= alpha_lo; o[nt][1] *= alpha_lo;
                o[nt][2] *= alpha_hi; o[nt][3] *= alpha_hi;
            }

            unsigned pa[4][4];
            #pragma unroll
            for (int s = 0; s < 4; s++) {
                pa[s][0] = pack2(sc[2 * s][0], sc[2 * s][1]);
                pa[s][1] = pack2(sc[2 * s][2], sc[2 * s][3]);
                pa[s][2] = pack2(sc[2 * s + 1][0], sc[2 * s + 1][1]);
                pa[s][3] = pack2(sc[2 * s + 1][2], sc[2 * s + 1][3]);
            }

            #pragma unroll
            for (int s = 0; s < 4; s++) {
                unsigned vb[8][2];
                #pragma unroll
                for (int p = 0; p < 4; p++) {
                    int trow = s * 16 + (sel & 1) * 8 + lrow;
                    unsigned r0, r1, r2, r3;
                    ldsm_x4_t(r0, r1, r2, r3,
                              vs + trow * FSTB + (p * 2 + (sel >> 1)) * 16);
                    vb[p * 2][0] = r0; vb[p * 2][1] = r1;
                    vb[p * 2 + 1][0] = r2; vb[p * 2 + 1][1] = r3;
                }
                #pragma unroll
                for (int nt = 0; nt < 8; nt++)
                    mma_f16(o[nt], pa[s][0], pa[s][1], pa[s][2], pa[s][3],
                            vb[nt][0], vb[nt][1]);
            }
        }
        __syncthreads();   // all reads of slot kt&1 done before it is refilled
    }

    // epilogue: normalize, write fp16 [B,T,D]
    float inv_lo = 1.0f / l_lo;
    float inv_hi = 1.0f / l_hi;
    __half* out_lo = out + (size_t)(b * TT + q0 + rbase + gid    ) * DD + h * HD;
    __half* out_hi = out + (size_t)(b * TT + q0 + rbase + gid + 8) * DD + h * HD;
    #pragma unroll
    for (int nt = 0; nt < 8; nt++) {
        int cc = nt * 8 + tig * 2;
        *(unsigned*)(out_lo + cc) = pack2(o[nt][0] * inv_lo, o[nt][1] * inv_lo);
        *(unsigned*)(out_hi + cc) = pack2(o[nt][2] * inv_hi, o[nt][3] * inv_hi);
    }
}

// ---------------------------------------------------------------------------
extern "C" void kernel_launch(void* const* d_in, const int* in_sizes, int n_in,
                              void* d_out, int out_size)
{
    const float* x     = (const float*)d_in[0]; // [B,T,D]
    const float* w_qkv = (const float*)d_in[1]; // [D,3D]
    const float* w_out = (const float*)d_in[2]; // [D,D]
    float* out = (float*)d_out;                 // [B,T,D]

    __half *qkvh, *atth, *xh, *wqh, *woh;
    cudaGetSymbolAddress((void**)&qkvh, g_qkvh);
    cudaGetSymbolAddress((void**)&atth, g_atth);
    cudaGetSymbolAddress((void**)&xh, g_xh);
    cudaGetSymbolAddress((void**)&wqh, g_wqh);
    cudaGetSymbolAddress((void**)&woh, g_woh);

    cudaFuncSetAttribute(flash_f16, cudaFuncAttributeMaxDynamicSharedMemorySize,
                         FLASH_H_SMEM);

    const int M = BB * TT; // 4096
    const int nx = M * DD, nwq = DD * 3 * DD, nwo = DD * DD;

    // 0. convert inputs to fp16
    f2h_k<<<(nx  / 8 + 255) / 256, 256>>>(x, xh, nx);
    f2h_k<<<(nwq / 8 + 255) / 256, 256>>>(w_qkv, wqh, nwq);
    f2h_k<<<(nwo / 8 + 255) / 256, 256>>>(w_out, woh, nwo);

    // 1. qkv = x @ w_qkv with fused RoPE (fp16 tensor cores, fp16 out)
    gemm_f16<__half, true><<<dim3((3 * DD) / 128, M / 128), 256, GH_SMEM>>>(
        xh, wqh, qkvh, M, 3 * DD, DD);
    // 2. causal flash attention (fp16, cp.async-pipelined K/V) -> atth
    flash_f16<<<dim3(TT / 128, BB * HH), 256, FLASH_H_SMEM>>>(qkvh, atth);
    // 3. out = att @ w_out  (fp16 tensor cores, fp32 out)
    gemm_f16<float, false><<<dim3(DD / 128, M / 128), 256, GH_SMEM>>>(
        atth, woh, out, M, DD, DD);
}

// round 16
// speedup vs baseline: 7.6005x; 1.1130x over previous
#include <cuda_runtime.h>
#include <cuda_fp16.h>
#include <math.h>

// Problem constants
#define BB 2
#define TT 2048
#define DD 1024
#define HH 16
#define HD 64

// Scratch (device globals; no runtime allocation allowed)
__device__ __half g_qkvh[(size_t)BB * TT * 3 * DD]; // [B*T, 3D] q|k|v fp16 (rope applied)
__device__ __half g_atth[(size_t)BB * TT * DD];     // attention out, fp16
__device__ __half g_xh[(size_t)BB * TT * DD];       // x in fp16
__device__ __half g_wqh[(size_t)DD * 3 * DD];       // w_qkv fp16 [K][N]
__device__ __half g_woh[(size_t)DD * DD];           // w_out fp16 [K][N]

__device__ __forceinline__ unsigned pack2(float a, float b) {
    __half2 h = __floats2half2_rn(a, b);
    return *(unsigned*)&h;
}

__device__ __forceinline__ float ex2f(float x) {
    float r;
    asm("ex2.approx.ftz.f32 %0, %1;" : "=f"(r) : "f"(x));
    return r;
}

__device__ __forceinline__ void mma_f16(float c[4], unsigned a0, unsigned a1,
                                        unsigned a2, unsigned a3,
                                        unsigned b0, unsigned b1) {
    asm volatile(
        "mma.sync.aligned.m16n8k16.row.col.f32.f16.f16.f32 "
        "{%0,%1,%2,%3}, {%4,%5,%6,%7}, {%8,%9}, {%0,%1,%2,%3};\n"
        : "+f"(c[0]), "+f"(c[1]), "+f"(c[2]), "+f"(c[3])
        : "r"(a0), "r"(a1), "r"(a2), "r"(a3), "r"(b0), "r"(b1));
}

__device__ __forceinline__ void ldsm_x4(unsigned& r0, unsigned& r1,
                                        unsigned& r2, unsigned& r3, unsigned a) {
    asm volatile("ldmatrix.sync.aligned.m8n8.x4.shared.b16 {%0,%1,%2,%3}, [%4];"
                 : "=r"(r0), "=r"(r1), "=r"(r2), "=r"(r3) : "r"(a));
}
__device__ __forceinline__ void ldsm_x4_t(unsigned& r0, unsigned& r1,
                                          unsigned& r2, unsigned& r3, unsigned a) {
    asm volatile("ldmatrix.sync.aligned.m8n8.x4.trans.shared.b16 {%0,%1,%2,%3}, [%4];"
                 : "=r"(r0), "=r"(r1), "=r"(r2), "=r"(r3) : "r"(a));
}

__device__ __forceinline__ void cp_async16_s(unsigned saddr, const void* g) {
    asm volatile("cp.async.cg.shared.global [%0], [%1], 16;\n"
                 :: "r"(saddr), "l"(g));
}
#define CP_COMMIT() asm volatile("cp.async.commit_group;\n" ::: "memory")
#define CP_WAIT1()  asm volatile("cp.async.wait_group 1;\n" ::: "memory")

// ---------------------------------------------------------------------------
// Fused fp32 -> fp16 conversion of x, w_qkv, w_out (one launch).
// ---------------------------------------------------------------------------
#define NX  (BB * TT * DD)        // 8M ... actually 8,388,608? no: 2*2048*1024 = 4,194,304
#define NWQ (DD * 3 * DD)         // 3,145,728
#define NWO (DD * DD)             // 1,048,576

__global__ __launch_bounds__(256) void f2h_all(const float* __restrict__ x,
                                               const float* __restrict__ wq,
                                               const float* __restrict__ wo,
                                               __half* __restrict__ xh,
                                               __half* __restrict__ wqh,
                                               __half* __restrict__ woh)
{
    int i = (blockIdx.x * blockDim.x + threadIdx.x) * 8;
    const float* src;
    __half* dst;
    if (i < NX) { src = x + i; dst = xh + i; }
    else if (i < NX + NWQ) { src = wq + (i - NX); dst = wqh + (i - NX); }
    else if (i < NX + NWQ + NWO) { src = wo + (i - NX - NWQ); dst = woh + (i - NX - NWQ); }
    else return;
    float4 v0 = *(const float4*)src;
    float4 v1 = *(const float4*)(src + 4);
    uint4 u = make_uint4(pack2(v0.x, v0.y), pack2(v0.z, v0.w),
                         pack2(v1.x, v1.y), pack2(v1.z, v1.w));
    *(uint4*)dst = u;
}

// ---------------------------------------------------------------------------
// fp16 tensor-core GEMM: C[M,N] = A[M,K] @ B[K,N].
// 3-stage cp.async ring, ONE __syncthreads per k-tile.
// Warp's N cols are groups {wn*8 + nt*32} (RoPE-fusable epilogue).
// ---------------------------------------------------------------------------
#define BKH 32
#define A_ST 80
#define B_ST 272
#define A_STAGEB (128 * A_ST)
#define B_STAGEB (BKH * B_ST)
#define STAGEB (A_STAGEB + B_STAGEB)
#define GH_SMEM (3 * STAGEB)

template <typename OutT, bool ROPE>
__global__ __launch_bounds__(256, 2) void gemm_f16(const __half* __restrict__ A,
                                                   const __half* __restrict__ B,
                                                   OutT* __restrict__ C,
                                                   int M, int N, int K)
{
    extern __shared__ unsigned char hsm[];
    const unsigned sbase = (unsigned)__cvta_generic_to_shared(hsm);

    const int tid  = threadIdx.x;
    const int warp = tid >> 5;
    const int lane = tid & 31;
    const int wm   = warp >> 2;
    const int wn   = warp & 3;
    const int gid  = lane >> 2;
    const int tig  = lane & 3;
    const int sel  = lane >> 3;
    const int lrow = lane & 7;

    const int cRow = blockIdx.y * 128;
    const int cCol = blockIdx.x * 128;

    float c[4][4][4];
    #pragma unroll
    for (int mt = 0; mt < 4; mt++)
        #pragma unroll
        for (int nt = 0; nt < 4; nt++)
            #pragma unroll
            for (int r = 0; r < 4; r++) c[mt][nt][r] = 0.0f;

    const int ntiles = K / BKH;

    auto load_stage = [&](int t) {
        int slot = t % 3;
        unsigned bufA = sbase + slot * STAGEB;
        unsigned bufB = bufA + A_STAGEB;
        int k0 = t * BKH;
        #pragma unroll
        for (int j = 0; j < 2; j++) {
            int i = tid + j * 256;
            int r = i >> 2, cc = i & 3;
            cp_async16_s(bufA + r * A_ST + cc * 16,
                         A + (size_t)(cRow + r) * K + k0 + cc * 8);
            int k = i >> 4, bc = i & 15;
            cp_async16_s(bufB + k * B_ST + bc * 16,
                         B + (size_t)(k0 + k) * N + cCol + bc * 8);
        }
    };

    load_stage(0); CP_COMMIT();
    load_stage(1); CP_COMMIT();

    for (int t = 0; t < ntiles; t++) {
        CP_WAIT1();        // groups outstanding: t, t+1 -> t complete
        __syncthreads();   // t's data visible; slot (t+2)%3 drained (read in t-1)

        if (t + 2 < ntiles) load_stage(t + 2);
        CP_COMMIT();       // commit (possibly empty) keeps group accounting

        int slot = t % 3;
        unsigned bufA = sbase + slot * STAGEB;
        unsigned bufB = bufA + A_STAGEB;

        #pragma unroll
        for (int s = 0; s < 2; s++) {
            unsigned af[4][4];
            #pragma unroll
            for (int mt = 0; mt < 4; mt++) {
                int row = wm * 64 + mt * 16 + (sel & 1) * 8 + lrow;
                ldsm_x4(af[mt][0], af[mt][1], af[mt][2], af[mt][3],
                        bufA + row * A_ST + s * 32 + (sel >> 1) * 16);
            }
            unsigned bf[4][2];
            #pragma unroll
            for (int p = 0; p < 2; p++) {
                int krow = s * 16 + (sel & 1) * 8 + lrow;
                int ncol = wn * 8 + (sel >> 1) * 32 + p * 64;
                unsigned r0, r1, r2, r3;
                ldsm_x4_t(r0, r1, r2, r3, bufB + krow * B_ST + ncol * 2);
                bf[p * 2][0] = r0; bf[p * 2][1] = r1;
                bf[p * 2 + 1][0] = r2; bf[p * 2 + 1][1] = r3;
            }
            #pragma unroll
            for (int mt = 0; mt < 4; mt++)
                #pragma unroll
                for (int nt = 0; nt < 4; nt++)
                    mma_f16(c[mt][nt], af[mt][0], af[mt][1], af[mt][2], af[mt][3],
                            bf[nt][0], bf[nt][1]);
        }
    }

    // epilogue (optionally fused RoPE for q/k regions)
    const bool is_qk = ROPE && (cCol < 2 * DD);
    float inv0 = 0.0f, inv1 = 0.0f;
    if (is_qk) {
        float j0 = (float)(wn * 8 + tig * 2);
        inv0 = powf(10000.0f, -j0 * (1.0f / 32.0f));
        inv1 = powf(10000.0f, -(j0 + 1.0f) * (1.0f / 32.0f));
    }

    #pragma unroll
    for (int mt = 0; mt < 4; mt++) {
        int row = cRow + wm * 64 + mt * 16 + gid;
        if (is_qk) {
            int t0 = row & (TT - 1);
            int t1 = (row + 8) & (TT - 1);
            float s00, c00, s01, c01, s10, c10, s11, c11;
            sincosf((float)t0 * inv0, &s00, &c00);
            sincosf((float)t0 * inv1, &s01, &c01);
            sincosf((float)t1 * inv0, &s10, &c10);
            sincosf((float)t1 * inv1, &s11, &c11);
            #pragma unroll
            for (int p = 0; p < 4; p += 2) {
                float x1, x2;
                x1 = c[mt][p][0]; x2 = c[mt][p + 1][0];
                c[mt][p][0] = x1 * c00 - x2 * s00;
                c[mt][p + 1][0] = x2 * c00 + x1 * s00;
                x1 = c[mt][p][1]; x2 = c[mt][p + 1][1];
                c[mt][p][1] = x1 * c01 - x2 * s01;
                c[mt][p + 1][1] = x2 * c01 + x1 * s01;
                x1 = c[mt][p][2]; x2 = c[mt][p + 1][2];
                c[mt][p][2] = x1 * c10 - x2 * s10;
                c[mt][p + 1][2] = x2 * c10 + x1 * s10;
                x1 = c[mt][p][3]; x2 = c[mt][p + 1][3];
                c[mt][p][3] = x1 * c11 - x2 * s11;
                c[mt][p + 1][3] = x2 * c11 + x1 * s11;
            }
        }
        #pragma unroll
        for (int nt = 0; nt < 4; nt++) {
            int col = cCol + wn * 8 + nt * 32 + tig * 2;
            if (sizeof(OutT) == 4) {
                *(float2*)((float*)C + (size_t)row * N + col) =
                    make_float2(c[mt][nt][0], c[mt][nt][1]);
                *(float2*)((float*)C + (size_t)(row + 8) * N + col) =
                    make_float2(c[mt][nt][2], c[mt][nt][3]);
            } else {
                *(unsigned*)((__half*)C + (size_t)row * N + col) =
                    pack2(c[mt][nt][0], c[mt][nt][1]);
                *(unsigned*)((__half*)C + (size_t)(row + 8) * N + col) =
                    pack2(c[mt][nt][2], c[mt][nt][3]);
            }
        }
    }
}

// ---------------------------------------------------------------------------
// Causal flash attention, fp16 mma m16n8k16, exp2-domain softmax.
// Block = 128 q-rows of one (b,h), 256 threads / 8 warps; warp owns 16 rows.
// K/V 64-row tiles, 3-slot cp.async ring, ONE __syncthreads per k-tile.
// Q pre-scaled by log2(e)/8 so softmax uses raw ex2.
// ---------------------------------------------------------------------------
#define FST 72
#define FSTB 144
#define KV_SLOT (64 * FSTB)                       // 9216 B per K or V tile
#define FLASH_H_SMEM (128 * FSTB + 6 * KV_SLOT)   // Q + 3*(K+V) = 73728

__global__ __launch_bounds__(256) void flash_f16(const __half* __restrict__ qkv,
                                                 __half* __restrict__ out)
{
    extern __shared__ __half fsm[];
    const unsigned qs  = (unsigned)__cvta_generic_to_shared(fsm);
    const unsigned kv0 = qs + 128 * FSTB;   // 3 slots of [K V]

    const int qt = blockIdx.x;
    const int bh = blockIdx.y;
    const int b  = bh >> 4;
    const int h  = bh & 15;
    const int tid  = threadIdx.x;
    const int warp = tid >> 5;
    const int lane = tid & 31;
    const int gid  = lane >> 2;
    const int tig  = lane & 3;
    const int sel  = lane >> 3;
    const int lrow = lane & 7;
    const int rbase = warp * 16;

    const int q0 = qt * 128;
    const __half* qg = qkv + ((size_t)(b * TT + q0)) * (3 * DD) + h * HD;
    const __half* kgb = qkv + (size_t)b * TT * 3 * DD + DD + h * HD;
    const __half* vgb = qkv + (size_t)b * TT * 3 * DD + 2 * DD + h * HD;

    // Q -> smem, scaled by log2(e)/8 (exp2-domain softmax)
    const __half2 hscale = __float2half2_rn(0.125f * 1.44269504f);
    for (int i = tid; i < 1024; i += 256) {
        int r = i >> 3, cc = i & 7;
        uint4 u = *(const uint4*)(qg + (size_t)r * (3 * DD) + cc * 8);
        __half2* hp = (__half2*)&u;
        hp[0] = __hmul2(hp[0], hscale);
        hp[1] = __hmul2(hp[1], hscale);
        hp[2] = __hmul2(hp[2], hscale);
        hp[3] = __hmul2(hp[3], hscale);
        *(uint4*)((char*)fsm + r * FSTB + cc * 16) = u;
    }

    auto load_kv = [&](int kt) {
        unsigned base = kv0 + (kt % 3) * (2 * KV_SLOT);
        const __half* kg = kgb + (size_t)(kt * 64) * (3 * DD);
        const __half* vg = vgb + (size_t)(kt * 64) * (3 * DD);
        #pragma unroll
        for (int j = 0; j < 2; j++) {
            int i = tid + j * 256;
            int r = i >> 3, cc = i & 7;
            cp_async16_s(base + r * FSTB + cc * 16,
                         kg + (size_t)r * (3 * DD) + cc * 8);
            cp_async16_s(base + KV_SLOT + r * FSTB + cc * 16,
                         vg + (size_t)r * (3 * DD) + cc * 8);
        }
    };

    const int nkt = 2 * qt + 2;
    load_kv(0); CP_COMMIT();
    if (nkt > 1) load_kv(1);
    CP_COMMIT();

    __syncthreads();   // Q visible

    // Q fragments -> registers
    unsigned qf[4][4];
    #pragma unroll
    for (int s = 0; s < 4; s++) {
        int row = rbase + (sel & 1) * 8 + lrow;
        ldsm_x4(qf[s][0], qf[s][1], qf[s][2], qf[s][3],
                qs + row * FSTB + s * 32 + (sel >> 1) * 16);
    }

    float o[8][4];
    #pragma unroll
    for (int nt = 0; nt < 8; nt++)
        #pragma unroll
        for (int r = 0; r < 4; r++) o[nt][r] = 0.0f;
    float m_lo = -INFINITY, m_hi = -INFINITY;
    float l_lo = 0.0f, l_hi = 0.0f;

    const int row_lo = q0 + rbase + gid;
    const int row_hi = row_lo + 8;
    const int wrow_max = q0 + rbase + 15;

    for (int kt = 0; kt < nkt; kt++) {
        CP_WAIT1();        // groups: kt, kt+1 outstanding -> kt done
        __syncthreads();   // kt visible to all; slot (kt+2)%3 drained

        if (kt + 2 < nkt) load_kv(kt + 2);
        CP_COMMIT();       // keep group accounting exact

        const unsigned ks = kv0 + (kt % 3) * (2 * KV_SLOT);
        const unsigned vs = ks + KV_SLOT;
        const int k0 = kt * 64;

        if (k0 > wrow_max) continue;   // whole warp tile above diagonal

        // S = Q K^T (exp2 domain)
        float sc[8][4];
        #pragma unroll
        for (int nt = 0; nt < 8; nt++)
            #pragma unroll
            for (int r = 0; r < 4; r++) sc[nt][r] = 0.0f;

        #pragma unroll
        for (int s = 0; s < 4; s++) {
            unsigned kb[8][2];
            #pragma unroll
            for (int p = 0; p < 4; p++) {
                int trow = (p * 2 + (sel >> 1)) * 8 + lrow;
                unsigned r0, r1, r2, r3;
                ldsm_x4(r0, r1, r2, r3,
                        ks + trow * FSTB + s * 32 + (sel & 1) * 16);
                kb[p * 2][0] = r0; kb[p * 2][1] = r1;
                kb[p * 2 + 1][0] = r2; kb[p * 2 + 1][1] = r3;
            }
            #pragma unroll
            for (int nt = 0; nt < 8; nt++)
                mma_f16(sc[nt], qf[s][0], qf[s][1], qf[s][2], qf[s][3],
                        kb[nt][0], kb[nt][1]);
        }

        if (k0 + 63 > row_lo) {
            #pragma unroll
            for (int nt = 0; nt < 8; nt++) {
                int c0 = k0 + nt * 8 + tig * 2;
                if (c0     > row_lo) sc[nt][0] = -INFINITY;
                if (c0 + 1 > row_lo) sc[nt][1] = -INFINITY;
                if (c0     > row_hi) sc[nt][2] = -INFINITY;
                if (c0 + 1 > row_hi) sc[nt][3] = -INFINITY;
            }
        }

        float mx_lo = -INFINITY, mx_hi = -INFINITY;
        #pragma unroll
        for (int nt = 0; nt < 8; nt++) {
            mx_lo = fmaxf(mx_lo, fmaxf(sc[nt][0], sc[nt][1]));
            mx_hi = fmaxf(mx_hi, fmaxf(sc[nt][2], sc[nt][3]));
        }
        #pragma unroll
        for (int off = 1; off <= 2; off <<= 1) {
            mx_lo = fmaxf(mx_lo, __shfl_xor_sync(0xffffffffu, mx_lo, off));
            mx_hi = fmaxf(mx_hi, __shfl_xor_sync(0xffffffffu, mx_hi, off));
        }

        float newm_lo = fmaxf(m_lo, mx_lo);
        float newm_hi = fmaxf(m_hi, mx_hi);
        float alpha_lo = ex2f(m_lo - newm_lo);
        float alpha_hi = ex2f(m_hi - newm_hi);

        float sum_lo = 0.0f, sum_hi = 0.0f;
        #pragma unroll
        for (int nt = 0; nt < 8; nt++) {
            sc[nt][0] = ex2f(sc[nt][0] - newm_lo);
            sc[nt][1] = ex2f(sc[nt][1] - newm_lo);
            sc[nt][2] = ex2f(sc[nt][2] - newm_hi);
            sc[nt][3] = ex2f(sc[nt][3] - newm_hi);
            sum_lo += sc[nt][0] + sc[nt][1];
            sum_hi += sc[nt][2] + sc[nt][3];
        }
        #pragma unroll
        for (int off = 1; off <= 2; off <<= 1) {
            sum_lo += __shfl_xor_sync(0xffffffffu, sum_lo, off);
            sum_hi += __shfl_xor_sync(0xffffffffu, sum_hi, off);
        }

        l_lo = l_lo * alpha_lo + sum_lo;
        l_hi = l_hi * alpha_hi + sum_hi;
        m_lo = newm_lo;
        m_hi = newm_hi;

        #pragma unroll
        for (int nt = 0; nt < 8; nt++) {
            o[nt][0] *= alpha_lo; o[nt][1] *= alpha_lo;
            o[nt][2] *= alpha_hi; o[nt][3] *= alpha_hi;
        }

        unsigned pa[4][4];
        #pragma unroll
        for (int s = 0; s < 4; s++) {
            pa[s][0] = pack2(sc[2 * s][0], sc[2 * s][1]);
            pa[s][1] = pack2(sc[2 * s][2], sc[2 * s][3]);
            pa[s][2] = pack2(sc[2 * s + 1][0], sc[2 * s + 1][1]);
            pa[s][3] = pack2(sc[2 * s + 1][2], sc[2 * s + 1][3]);
        }

        #pragma unroll
        for (int s = 0; s < 4; s++) {
            unsigned vb[8][2];
            #pragma unroll
            for (int p = 0; p < 4; p++) {
                int trow = s * 16 + (sel & 1) * 8 + lrow;
                unsigned r0, r1, r2, r3;
                ldsm_x4_t(r0, r1, r2, r3,
                          vs + trow * FSTB + (p * 2 + (sel >> 1)) * 16);
                vb[p * 2][0] = r0; vb[p * 2][1] = r1;
                vb[p * 2 + 1][0] = r2; vb[p * 2 + 1][1] = r3;
            }
            #pragma unroll
            for (int nt = 0; nt < 8; nt++)
                mma_f16(o[nt], pa[s][0], pa[s][1], pa[s][2], pa[s][3],
                        vb[nt][0], vb[nt][1]);
        }
    }

    // epilogue: normalize, write fp16 [B,T,D]
    float inv_lo = 1.0f / l_lo;
    float inv_hi = 1.0f / l_hi;
    __half* out_lo = out + (size_t)(b * TT + q0 + rbase + gid    ) * DD + h * HD;
    __half* out_hi = out + (size_t)(b * TT + q0 + rbase + gid + 8) * DD + h * HD;
    #pragma unroll
    for (int nt = 0; nt < 8; nt++) {
        int cc = nt * 8 + tig * 2;
        *(unsigned*)(out_lo + cc) = pack2(o[nt][0] * inv_lo, o[nt][1] * inv_lo);
        *(unsigned*)(out_hi + cc) = pack2(o[nt][2] * inv_hi, o[nt][3] * inv_hi);
    }
}

// ---------------------------------------------------------------------------
extern "C" void kernel_launch(void* const* d_in, const int* in_sizes, int n_in,
                              void* d_out, int out_size)
{
    const float* x     = (const float*)d_in[0]; // [B,T,D]
    const float* w_qkv = (const float*)d_in[1]; // [D,3D]
    const float* w_out = (const float*)d_in[2]; // [D,D]
    float* out = (float*)d_out;                 // [B,T,D]

    __half *qkvh, *atth, *xh, *wqh, *woh;
    cudaGetSymbolAddress((void**)&qkvh, g_qkvh);
    cudaGetSymbolAddress((void**)&atth, g_atth);
    cudaGetSymbolAddress((void**)&xh, g_xh);
    cudaGetSymbolAddress((void**)&wqh, g_wqh);
    cudaGetSymbolAddress((void**)&woh, g_woh);

    cudaFuncSetAttribute(flash_f16, cudaFuncAttributeMaxDynamicSharedMemorySize,
                         FLASH_H_SMEM);
    cudaFuncSetAttribute(gemm_f16<__half, true>,
                         cudaFuncAttributeMaxDynamicSharedMemorySize, GH_SMEM);
    cudaFuncSetAttribute(gemm_f16<float, false>,
                         cudaFuncAttributeMaxDynamicSharedMemorySize, GH_SMEM);

    const int M = BB * TT; // 4096
    const int ntot = NX + NWQ + NWO;

    // 0. convert inputs to fp16 (single launch)
    f2h_all<<<(ntot / 8 + 255) / 256, 256>>>(x, w_qkv, w_out, xh, wqh, woh);

    // 1. qkv = x @ w_qkv with fused RoPE (fp16 tensor cores, fp16 out)
    gemm_f16<__half, true><<<dim3((3 * DD) / 128, M / 128), 256, GH_SMEM>>>(
        xh, wqh, qkvh, M, 3 * DD, DD);
    // 2. causal flash attention (fp16, 3-slot cp.async ring) -> atth
    flash_f16<<<dim3(TT / 128, BB * HH), 256, FLASH_H_SMEM>>>(qkvh, atth);
    // 3. out = att @ w_out  (fp16 tensor cores, fp32 out)
    gemm_f16<float, false><<<dim3(DD / 128, M / 128), 256, GH_SMEM>>>(
        atth, woh, out, M, DD, DD);
}

// round 17
// speedup vs baseline: 8.3947x; 1.1045x over previous
#include <cuda_runtime.h>
#include <cuda_fp16.h>
#include <math.h>

// Problem constants
#define BB 2
#define TT 2048
#define DD 1024
#define HH 16
#define HD 64

// Scratch (device globals; no runtime allocation allowed)
__device__ __half g_qkvh[(size_t)BB * TT * 3 * DD]; // [B*T, 3D] q|k|v fp16 (rope applied)
__device__ __half g_atth[(size_t)BB * TT * DD];     // attention out, fp16
__device__ __half g_xh[(size_t)BB * TT * DD];       // x in fp16
__device__ __half g_wqh[(size_t)DD * 3 * DD];       // w_qkv fp16 [K][N]
__device__ __half g_woh[(size_t)DD * DD];           // w_out fp16 [K][N]

__device__ __forceinline__ unsigned pack2(float a, float b) {
    __half2 h = __floats2half2_rn(a, b);
    return *(unsigned*)&h;
}

__device__ __forceinline__ float ex2f(float x) {
    float r;
    asm("ex2.approx.ftz.f32 %0, %1;" : "=f"(r) : "f"(x));
    return r;
}

__device__ __forceinline__ void mma_f16(float c[4], unsigned a0, unsigned a1,
                                        unsigned a2, unsigned a3,
                                        unsigned b0, unsigned b1) {
    asm volatile(
        "mma.sync.aligned.m16n8k16.row.col.f32.f16.f16.f32 "
        "{%0,%1,%2,%3}, {%4,%5,%6,%7}, {%8,%9}, {%0,%1,%2,%3};\n"
        : "+f"(c[0]), "+f"(c[1]), "+f"(c[2]), "+f"(c[3])
        : "r"(a0), "r"(a1), "r"(a2), "r"(a3), "r"(b0), "r"(b1));
}

__device__ __forceinline__ void ldsm_x4(unsigned& r0, unsigned& r1,
                                        unsigned& r2, unsigned& r3, unsigned a) {
    asm volatile("ldmatrix.sync.aligned.m8n8.x4.shared.b16 {%0,%1,%2,%3}, [%4];"
                 : "=r"(r0), "=r"(r1), "=r"(r2), "=r"(r3) : "r"(a));
}
__device__ __forceinline__ void ldsm_x4_t(unsigned& r0, unsigned& r1,
                                          unsigned& r2, unsigned& r3, unsigned a) {
    asm volatile("ldmatrix.sync.aligned.m8n8.x4.trans.shared.b16 {%0,%1,%2,%3}, [%4];"
                 : "=r"(r0), "=r"(r1), "=r"(r2), "=r"(r3) : "r"(a));
}

__device__ __forceinline__ void cp_async16_s(unsigned saddr, const void* g) {
    asm volatile("cp.async.cg.shared.global [%0], [%1], 16;\n"
                 :: "r"(saddr), "l"(g));
}
#define CP_COMMIT() asm volatile("cp.async.commit_group;\n" ::: "memory")
#define CP_WAIT1()  asm volatile("cp.async.wait_group 1;\n" ::: "memory")

// ---------------------------------------------------------------------------
// Fused fp32 -> fp16 conversion of x, w_qkv, w_out (one launch).
// ---------------------------------------------------------------------------
#define NX  (BB * TT * DD)        // 4,194,304
#define NWQ (DD * 3 * DD)         // 3,145,728
#define NWO (DD * DD)             // 1,048,576

__global__ __launch_bounds__(256) void f2h_all(const float* __restrict__ x,
                                               const float* __restrict__ wq,
                                               const float* __restrict__ wo,
                                               __half* __restrict__ xh,
                                               __half* __restrict__ wqh,
                                               __half* __restrict__ woh)
{
    int i = (blockIdx.x * blockDim.x + threadIdx.x) * 8;
    const float* src;
    __half* dst;
    if (i < NX) { src = x + i; dst = xh + i; }
    else if (i < NX + NWQ) { src = wq + (i - NX); dst = wqh + (i - NX); }
    else if (i < NX + NWQ + NWO) { src = wo + (i - NX - NWQ); dst = woh + (i - NX - NWQ); }
    else return;
    float4 v0 = *(const float4*)src;
    float4 v1 = *(const float4*)(src + 4);
    uint4 u = make_uint4(pack2(v0.x, v0.y), pack2(v0.z, v0.w),
                         pack2(v1.x, v1.y), pack2(v1.z, v1.w));
    *(uint4*)dst = u;
}

// ---------------------------------------------------------------------------
// fp16 tensor-core GEMM: C[M,N] = A[M,K] @ B[K,N].
// 3-stage cp.async ring, ONE __syncthreads per k-tile.
// Warp's N cols are groups {wn*8 + nt*32} (RoPE-fusable epilogue).
// ---------------------------------------------------------------------------
#define BKH 32
#define A_ST 80
#define B_ST 272
#define A_STAGEB (128 * A_ST)
#define B_STAGEB (BKH * B_ST)
#define STAGEB (A_STAGEB + B_STAGEB)
#define GH_SMEM (3 * STAGEB)

template <typename OutT, bool ROPE>
__global__ __launch_bounds__(256, 2) void gemm_f16(const __half* __restrict__ A,
                                                   const __half* __restrict__ B,
                                                   OutT* __restrict__ C,
                                                   int M, int N, int K)
{
    extern __shared__ unsigned char hsm[];
    const unsigned sbase = (unsigned)__cvta_generic_to_shared(hsm);

    const int tid  = threadIdx.x;
    const int warp = tid >> 5;
    const int lane = tid & 31;
    const int wm   = warp >> 2;
    const int wn   = warp & 3;
    const int gid  = lane >> 2;
    const int tig  = lane & 3;
    const int sel  = lane >> 3;
    const int lrow = lane & 7;

    const int cRow = blockIdx.y * 128;
    const int cCol = blockIdx.x * 128;

    float c[4][4][4];
    #pragma unroll
    for (int mt = 0; mt < 4; mt++)
        #pragma unroll
        for (int nt = 0; nt < 4; nt++)
            #pragma unroll
            for (int r = 0; r < 4; r++) c[mt][nt][r] = 0.0f;

    const int ntiles = K / BKH;

    auto load_stage = [&](int t) {
        int slot = t % 3;
        unsigned bufA = sbase + slot * STAGEB;
        unsigned bufB = bufA + A_STAGEB;
        int k0 = t * BKH;
        #pragma unroll
        for (int j = 0; j < 2; j++) {
            int i = tid + j * 256;
            int r = i >> 2, cc = i & 3;
            cp_async16_s(bufA + r * A_ST + cc * 16,
                         A + (size_t)(cRow + r) * K + k0 + cc * 8);
            int k = i >> 4, bc = i & 15;
            cp_async16_s(bufB + k * B_ST + bc * 16,
                         B + (size_t)(k0 + k) * N + cCol + bc * 8);
        }
    };

    load_stage(0); CP_COMMIT();
    load_stage(1); CP_COMMIT();

    for (int t = 0; t < ntiles; t++) {
        CP_WAIT1();
        __syncthreads();

        if (t + 2 < ntiles) load_stage(t + 2);
        CP_COMMIT();

        int slot = t % 3;
        unsigned bufA = sbase + slot * STAGEB;
        unsigned bufB = bufA + A_STAGEB;

        #pragma unroll
        for (int s = 0; s < 2; s++) {
            unsigned af[4][4];
            #pragma unroll
            for (int mt = 0; mt < 4; mt++) {
                int row = wm * 64 + mt * 16 + (sel & 1) * 8 + lrow;
                ldsm_x4(af[mt][0], af[mt][1], af[mt][2], af[mt][3],
                        bufA + row * A_ST + s * 32 + (sel >> 1) * 16);
            }
            unsigned bf[4][2];
            #pragma unroll
            for (int p = 0; p < 2; p++) {
                int krow = s * 16 + (sel & 1) * 8 + lrow;
                int ncol = wn * 8 + (sel >> 1) * 32 + p * 64;
                unsigned r0, r1, r2, r3;
                ldsm_x4_t(r0, r1, r2, r3, bufB + krow * B_ST + ncol * 2);
                bf[p * 2][0] = r0; bf[p * 2][1] = r1;
                bf[p * 2 + 1][0] = r2; bf[p * 2 + 1][1] = r3;
            }
            #pragma unroll
            for (int mt = 0; mt < 4; mt++)
                #pragma unroll
                for (int nt = 0; nt < 4; nt++)
                    mma_f16(c[mt][nt], af[mt][0], af[mt][1], af[mt][2], af[mt][3],
                            bf[nt][0], bf[nt][1]);
        }
    }

    // epilogue (optionally fused RoPE for q/k regions)
    const bool is_qk = ROPE && (cCol < 2 * DD);
    float inv0 = 0.0f, inv1 = 0.0f;
    if (is_qk) {
        float j0 = (float)(wn * 8 + tig * 2);
        inv0 = powf(10000.0f, -j0 * (1.0f / 32.0f));
        inv1 = powf(10000.0f, -(j0 + 1.0f) * (1.0f / 32.0f));
    }

    #pragma unroll
    for (int mt = 0; mt < 4; mt++) {
        int row = cRow + wm * 64 + mt * 16 + gid;
        if (is_qk) {
            int t0 = row & (TT - 1);
            int t1 = (row + 8) & (TT - 1);
            float s00, c00, s01, c01, s10, c10, s11, c11;
            sincosf((float)t0 * inv0, &s00, &c00);
            sincosf((float)t0 * inv1, &s01, &c01);
            sincosf((float)t1 * inv0, &s10, &c10);
            sincosf((float)t1 * inv1, &s11, &c11);
            #pragma unroll
            for (int p = 0; p < 4; p += 2) {
                float x1, x2;
                x1 = c[mt][p][0]; x2 = c[mt][p + 1][0];
                c[mt][p][0] = x1 * c00 - x2 * s00;
                c[mt][p + 1][0] = x2 * c00 + x1 * s00;
                x1 = c[mt][p][1]; x2 = c[mt][p + 1][1];
                c[mt][p][1] = x1 * c01 - x2 * s01;
                c[mt][p + 1][1] = x2 * c01 + x1 * s01;
                x1 = c[mt][p][2]; x2 = c[mt][p + 1][2];
                c[mt][p][2] = x1 * c10 - x2 * s10;
                c[mt][p + 1][2] = x2 * c10 + x1 * s10;
                x1 = c[mt][p][3]; x2 = c[mt][p + 1][3];
                c[mt][p][3] = x1 * c11 - x2 * s11;
                c[mt][p + 1][3] = x2 * c11 + x1 * s11;
            }
        }
        #pragma unroll
        for (int nt = 0; nt < 4; nt++) {
            int col = cCol + wn * 8 + nt * 32 + tig * 2;
            if (sizeof(OutT) == 4) {
                *(float2*)((float*)C + (size_t)row * N + col) =
                    make_float2(c[mt][nt][0], c[mt][nt][1]);
                *(float2*)((float*)C + (size_t)(row + 8) * N + col) =
                    make_float2(c[mt][nt][2], c[mt][nt][3]);
            } else {
                *(unsigned*)((__half*)C + (size_t)row * N + col) =
                    pack2(c[mt][nt][0], c[mt][nt][1]);
                *(unsigned*)((__half*)C + (size_t)(row + 8) * N + col) =
                    pack2(c[mt][nt][2], c[mt][nt][3]);
            }
        }
    }
}

// ---------------------------------------------------------------------------
// Causal flash attention, fp16 mma m16n8k16, exp2-domain softmax.
// Grid (bh=32, qtidx=16), qt = 15 - blockIdx.y  => LPT scheduling: the
// longest (highest-qt) blocks are issued first, minimizing wave-2 tail.
// Block = 128 q-rows, 256 threads / 8 warps; K/V 64-row tiles, 3-slot ring.
// ---------------------------------------------------------------------------
#define FST 72
#define FSTB 144
#define KV_SLOT (64 * FSTB)
#define FLASH_H_SMEM (128 * FSTB + 6 * KV_SLOT)   // 73728

__global__ __launch_bounds__(256) void flash_f16(const __half* __restrict__ qkv,
                                                 __half* __restrict__ out)
{
    extern __shared__ __half fsm[];
    const unsigned qs  = (unsigned)__cvta_generic_to_shared(fsm);
    const unsigned kv0 = qs + 128 * FSTB;

    const int qt = (TT / 128 - 1) - blockIdx.y;   // LPT: longest first
    const int bh = blockIdx.x;
    const int b  = bh >> 4;
    const int h  = bh & 15;
    const int tid  = threadIdx.x;
    const int warp = tid >> 5;
    const int lane = tid & 31;
    const int gid  = lane >> 2;
    const int tig  = lane & 3;
    const int sel  = lane >> 3;
    const int lrow = lane & 7;
    const int rbase = warp * 16;

    const int q0 = qt * 128;
    const __half* qg = qkv + ((size_t)(b * TT + q0)) * (3 * DD) + h * HD;
    const __half* kgb = qkv + (size_t)b * TT * 3 * DD + DD + h * HD;
    const __half* vgb = qkv + (size_t)b * TT * 3 * DD + 2 * DD + h * HD;

    // Q -> smem, scaled by log2(e)/8 (exp2-domain softmax)
    const __half2 hscale = __float2half2_rn(0.125f * 1.44269504f);
    for (int i = tid; i < 1024; i += 256) {
        int r = i >> 3, cc = i & 7;
        uint4 u = *(const uint4*)(qg + (size_t)r * (3 * DD) + cc * 8);
        __half2* hp = (__half2*)&u;
        hp[0] = __hmul2(hp[0], hscale);
        hp[1] = __hmul2(hp[1], hscale);
        hp[2] = __hmul2(hp[2], hscale);
        hp[3] = __hmul2(hp[3], hscale);
        *(uint4*)((char*)fsm + r * FSTB + cc * 16) = u;
    }

    auto load_kv = [&](int kt) {
        unsigned base = kv0 + (kt % 3) * (2 * KV_SLOT);
        const __half* kg = kgb + (size_t)(kt * 64) * (3 * DD);
        const __half* vg = vgb + (size_t)(kt * 64) * (3 * DD);
        #pragma unroll
        for (int j = 0; j < 2; j++) {
            int i = tid + j * 256;
            int r = i >> 3, cc = i & 7;
            cp_async16_s(base + r * FSTB + cc * 16,
                         kg + (size_t)r * (3 * DD) + cc * 8);
            cp_async16_s(base + KV_SLOT + r * FSTB + cc * 16,
                         vg + (size_t)r * (3 * DD) + cc * 8);
        }
    };

    const int nkt = 2 * qt + 2;
    load_kv(0); CP_COMMIT();
    if (nkt > 1) load_kv(1);
    CP_COMMIT();

    __syncthreads();   // Q visible

    unsigned qf[4][4];
    #pragma unroll
    for (int s = 0; s < 4; s++) {
        int row = rbase + (sel & 1) * 8 + lrow;
        ldsm_x4(qf[s][0], qf[s][1], qf[s][2], qf[s][3],
                qs + row * FSTB + s * 32 + (sel >> 1) * 16);
    }

    float o[8][4];
    #pragma unroll
    for (int nt = 0; nt < 8; nt++)
        #pragma unroll
        for (int r = 0; r < 4; r++) o[nt][r] = 0.0f;
    float m_lo = -INFINITY, m_hi = -INFINITY;
    float l_lo = 0.0f, l_hi = 0.0f;

    const int row_lo = q0 + rbase + gid;
    const int row_hi = row_lo + 8;
    const int wrow_max = q0 + rbase + 15;

    for (int kt = 0; kt < nkt; kt++) {
        CP_WAIT1();
        __syncthreads();

        if (kt + 2 < nkt) load_kv(kt + 2);
        CP_COMMIT();

        const unsigned ks = kv0 + (kt % 3) * (2 * KV_SLOT);
        const unsigned vs = ks + KV_SLOT;
        const int k0 = kt * 64;

        if (k0 > wrow_max) continue;

        float sc[8][4];
        #pragma unroll
        for (int nt = 0; nt < 8; nt++)
            #pragma unroll
            for (int r = 0; r < 4; r++) sc[nt][r] = 0.0f;

        #pragma unroll
        for (int s = 0; s < 4; s++) {
            unsigned kb[8][2];
            #pragma unroll
            for (int p = 0; p < 4; p++) {
                int trow = (p * 2 + (sel >> 1)) * 8 + lrow;
                unsigned r0, r1, r2, r3;
                ldsm_x4(r0, r1, r2, r3,
                        ks + trow * FSTB + s * 32 + (sel & 1) * 16);
                kb[p * 2][0] = r0; kb[p * 2][1] = r1;
                kb[p * 2 + 1][0] = r2; kb[p * 2 + 1][1] = r3;
            }
            #pragma unroll
            for (int nt = 0; nt < 8; nt++)
                mma_f16(sc[nt], qf[s][0], qf[s][1], qf[s][2], qf[s][3],
                        kb[nt][0], kb[nt][1]);
        }

        if (k0 + 63 > row_lo) {
            #pragma unroll
            for (int nt = 0; nt < 8; nt++) {
                int c0 = k0 + nt * 8 + tig * 2;
                if (c0     > row_lo) sc[nt][0] = -INFINITY;
                if (c0 + 1 > row_lo) sc[nt][1] = -INFINITY;
                if (c0     > row_hi) sc[nt][2] = -INFINITY;
                if (c0 + 1 > row_hi) sc[nt][3] = -INFINITY;
            }
        }

        float mx_lo = -INFINITY, mx_hi = -INFINITY;
        #pragma unroll
        for (int nt = 0; nt < 8; nt++) {
            mx_lo = fmaxf(mx_lo, fmaxf(sc[nt][0], sc[nt][1]));
            mx_hi = fmaxf(mx_hi, fmaxf(sc[nt][2], sc[nt][3]));
        }
        #pragma unroll
        for (int off = 1; off <= 2; off <<= 1) {
            mx_lo = fmaxf(mx_lo, __shfl_xor_sync(0xffffffffu, mx_lo, off));
            mx_hi = fmaxf(mx_hi, __shfl_xor_sync(0xffffffffu, mx_hi, off));
        }

        float newm_lo = fmaxf(m_lo, mx_lo);
        float newm_hi = fmaxf(m_hi, mx_hi);
        float alpha_lo = ex2f(m_lo - newm_lo);
        float alpha_hi = ex2f(m_hi - newm_hi);

        float sum_lo = 0.0f, sum_hi = 0.0f;
        #pragma unroll
        for (int nt = 0; nt < 8; nt++) {
            sc[nt][0] = ex2f(sc[nt][0] - newm_lo);
            sc[nt][1] = ex2f(sc[nt][1] - newm_lo);
            sc[nt][2] = ex2f(sc[nt][2] - newm_hi);
            sc[nt][3] = ex2f(sc[nt][3] - newm_hi);
            sum_lo += sc[nt][0] + sc[nt][1];
            sum_hi += sc[nt][2] + sc[nt][3];
        }
        #pragma unroll
        for (int off = 1; off <= 2; off <<= 1) {
            sum_lo += __shfl_xor_sync(0xffffffffu, sum_lo, off);
            sum_hi += __shfl_xor_sync(0xffffffffu, sum_hi, off);
        }

        l_lo = l_lo * alpha_lo + sum_lo;
        l_hi = l_hi * alpha_hi + sum_hi;
        m_lo = newm_lo;
        m_hi = newm_hi;

        #pragma unroll
        for (int nt = 0; nt < 8; nt++) {
            o[nt][0] *= alpha_lo; o[nt][1] *= alpha_lo;
            o[nt][2] *= alpha_hi; o[nt][3] *= alpha_hi;
        }

        unsigned pa[4][4];
        #pragma unroll
        for (int s = 0; s < 4; s++) {
            pa[s][0] = pack2(sc[2 * s][0], sc[2 * s][1]);
            pa[s][1] = pack2(sc[2 * s][2], sc[2 * s][3]);
            pa[s][2] = pack2(sc[2 * s + 1][0], sc[2 * s + 1][1]);
            pa[s][3] = pack2(sc[2 * s + 1][2], sc[2 * s + 1][3]);
        }

        #pragma unroll
        for (int s = 0; s < 4; s++) {
            unsigned vb[8][2];
            #pragma unroll
            for (int p = 0; p < 4; p++) {
                int trow = s * 16 + (sel & 1) * 8 + lrow;
                unsigned r0, r1, r2, r3;
                ldsm_x4_t(r0, r1, r2, r3,
                          vs + trow * FSTB + (p * 2 + (sel >> 1)) * 16);
                vb[p * 2][0] = r0; vb[p * 2][1] = r1;
                vb[p * 2 + 1][0] = r2; vb[p * 2 + 1][1] = r3;
            }
            #pragma unroll
            for (int nt = 0; nt < 8; nt++)
                mma_f16(o[nt], pa[s][0], pa[s][1], pa[s][2], pa[s][3],
                        vb[nt][0], vb[nt][1]);
        }
    }

    // epilogue: normalize, write fp16 [B,T,D]
    float inv_lo = 1.0f / l_lo;
    float inv_hi = 1.0f / l_hi;
    __half* out_lo = out + (size_t)(b * TT + q0 + rbase + gid    ) * DD + h * HD;
    __half* out_hi = out + (size_t)(b * TT + q0 + rbase + gid + 8) * DD + h * HD;
    #pragma unroll
    for (int nt = 0; nt < 8; nt++) {
        int cc = nt * 8 + tig * 2;
        *(unsigned*)(out_lo + cc) = pack2(o[nt][0] * inv_lo, o[nt][1] * inv_lo);
        *(unsigned*)(out_hi + cc) = pack2(o[nt][2] * inv_hi, o[nt][3] * inv_hi);
    }
}

// ---------------------------------------------------------------------------
extern "C" void kernel_launch(void* const* d_in, const int* in_sizes, int n_in,
                              void* d_out, int out_size)
{
    const float* x     = (const float*)d_in[0]; // [B,T,D]
    const float* w_qkv = (const float*)d_in[1]; // [D,3D]
    const float* w_out = (const float*)d_in[2]; // [D,D]
    float* out = (float*)d_out;                 // [B,T,D]

    __half *qkvh, *atth, *xh, *wqh, *woh;
    cudaGetSymbolAddress((void**)&qkvh, g_qkvh);
    cudaGetSymbolAddress((void**)&atth, g_atth);
    cudaGetSymbolAddress((void**)&xh, g_xh);
    cudaGetSymbolAddress((void**)&wqh, g_wqh);
    cudaGetSymbolAddress((void**)&woh, g_woh);

    cudaFuncSetAttribute(flash_f16, cudaFuncAttributeMaxDynamicSharedMemorySize,
                         FLASH_H_SMEM);
    cudaFuncSetAttribute(gemm_f16<__half, true>,
                         cudaFuncAttributeMaxDynamicSharedMemorySize, GH_SMEM);
    cudaFuncSetAttribute(gemm_f16<float, false>,
                         cudaFuncAttributeMaxDynamicSharedMemorySize, GH_SMEM);

    const int M = BB * TT; // 4096
    const int ntot = NX + NWQ + NWO;

    // 0. convert inputs to fp16 (single launch)
    f2h_all<<<(ntot / 8 + 255) / 256, 256>>>(x, w_qkv, w_out, xh, wqh, woh);

    // 1. qkv = x @ w_qkv with fused RoPE (fp16 tensor cores, fp16 out)
    gemm_f16<__half, true><<<dim3((3 * DD) / 128, M / 128), 256, GH_SMEM>>>(
        xh, wqh, qkvh, M, 3 * DD, DD);
    // 2. causal flash attention (fp16, LPT-scheduled) -> atth
    flash_f16<<<dim3(BB * HH, TT / 128), 256, FLASH_H_SMEM>>>(qkvh, atth);
    // 3. out = att @ w_out  (fp16 tensor cores, fp32 out)
    gemm_f16<float, false><<<dim3(DD / 128, M / 128), 256, GH_SMEM>>>(
        atth, woh, out, M, DD, DD);
}